// round 1
// baseline (speedup 1.0000x reference)
#include <cuda_runtime.h>

#define HH 8
#define NNS 1024
#define DDim 64
#define MMf 128
#define CC 64
#define NCH 16   // NNS / CC
#define EPSF 1e-3f
#define NORMF 0.35355339059327373f   // 64^-0.25

// ---- scratch (static device arrays; no allocations allowed) ----
__device__ float g_qp[HH*NNS*MMf];          // 4 MB
__device__ float g_kp[HH*NNS*MMf];          // 4 MB
__device__ float g_Sc[HH*NCH*MMf*DDim];     // 4 MB  per-chunk K^T V sums
__device__ float g_Sp[HH*NCH*MMf*DDim];     // 4 MB  exclusive prefix
__device__ float g_zc[HH*NCH*MMf];
__device__ float g_zp[HH*NCH*MMf];

// ============================================================
// Kernel 1: feature map  xp = relu((x*norm) @ proj^T) + eps
// grid (NCH, HH, 2): z=0 -> q, z=1 -> k.  block 256.
// ============================================================
__global__ void k_feat(const float* __restrict__ q,
                       const float* __restrict__ k,
                       const float* __restrict__ proj) {
    extern __shared__ float sm[];
    float* xs = sm;               // [CC][DDim]   16 KB
    float* ps = sm + CC*DDim;     // [DDim][MMf]  32 KB (proj transposed)
    const int nt = blockIdx.x, h = blockIdx.y;
    const float* x = blockIdx.z ? k : q;
    float* xp = blockIdx.z ? g_kp : g_qp;
    const int tid = threadIdx.x;

    for (int i = tid; i < MMf*DDim; i += 256) {
        int m = i / DDim, d = i - m*DDim;
        ps[d*MMf + m] = proj[i];
    }
    const float* xb = x + (h*NNS + nt*CC)*DDim;
    for (int i = tid; i < CC*DDim; i += 256)
        xs[i] = xb[i] * NORMF;
    __syncthreads();

    const int tx = tid & 15;       // m group: 8 cols
    const int ty = tid >> 4;       // n group: 4 rows
    float acc[4][8];
    #pragma unroll
    for (int r = 0; r < 4; r++)
        #pragma unroll
        for (int c = 0; c < 8; c++) acc[r][c] = 0.f;

    #pragma unroll 4
    for (int d = 0; d < DDim; d++) {
        float a[4], b[8];
        #pragma unroll
        for (int r = 0; r < 4; r++) a[r] = xs[(ty*4+r)*DDim + d];
        #pragma unroll
        for (int c = 0; c < 8; c++) b[c] = ps[d*MMf + tx*8 + c];
        #pragma unroll
        for (int r = 0; r < 4; r++)
            #pragma unroll
            for (int c = 0; c < 8; c++) acc[r][c] = fmaf(a[r], b[c], acc[r][c]);
    }
    float* ob = xp + (h*NNS + nt*CC)*MMf;
    #pragma unroll
    for (int r = 0; r < 4; r++)
        #pragma unroll
        for (int c = 0; c < 8; c++)
            ob[(ty*4+r)*MMf + tx*8 + c] = fmaxf(acc[r][c], 0.f) + EPSF;
}

// ============================================================
// Kernel 2: per-chunk sums  S_c = Kp_c^T @ V_c,  z_c = sum_j kp
// grid (NCH, HH), block 256.
// ============================================================
__global__ void k_chunksum(const float* __restrict__ v) {
    extern __shared__ float sm[];
    float* kps = sm;              // [CC][MMf] 32 KB
    float* vs  = sm + CC*MMf;     // [CC][DDim] 16 KB
    const int c = blockIdx.x, h = blockIdx.y, tid = threadIdx.x;

    const float* kb = g_kp + (h*NNS + c*CC)*MMf;
    for (int i = tid; i < CC*MMf; i += 256) kps[i] = kb[i];
    const float* vb = v + (h*NNS + c*CC)*DDim;
    for (int i = tid; i < CC*DDim; i += 256) vs[i] = vb[i];
    __syncthreads();

    const int tx = tid & 15;      // d group: 4
    const int ty = tid >> 4;      // m group: 8
    float acc[8][4];
    #pragma unroll
    for (int r = 0; r < 8; r++)
        #pragma unroll
        for (int cc = 0; cc < 4; cc++) acc[r][cc] = 0.f;

    #pragma unroll 2
    for (int j = 0; j < CC; j++) {
        float a[8], b[4];
        #pragma unroll
        for (int r = 0; r < 8; r++) a[r] = kps[j*MMf + ty*8 + r];
        #pragma unroll
        for (int cc = 0; cc < 4; cc++) b[cc] = vs[j*DDim + tx*4 + cc];
        #pragma unroll
        for (int r = 0; r < 8; r++)
            #pragma unroll
            for (int cc = 0; cc < 4; cc++) acc[r][cc] = fmaf(a[r], b[cc], acc[r][cc]);
    }
    float* Sb = g_Sc + (h*NCH + c)*MMf*DDim;
    #pragma unroll
    for (int r = 0; r < 8; r++)
        #pragma unroll
        for (int cc = 0; cc < 4; cc++)
            Sb[(ty*8+r)*DDim + tx*4 + cc] = acc[r][cc];

    if (tid < MMf) {
        float z = 0.f;
        #pragma unroll 8
        for (int j = 0; j < CC; j++) z += kps[j*MMf + tid];
        g_zc[(h*NCH + c)*MMf + tid] = z;
    }
}

// ============================================================
// Kernel 3: exclusive prefix over chunks. grid HH, block 512.
// ============================================================
__global__ void k_prefix() {
    const int h = blockIdx.x, tid = threadIdx.x;
    for (int i = tid; i < MMf*DDim; i += 512) {
        float run = 0.f;
        #pragma unroll
        for (int c = 0; c < NCH; c++) {
            int idx = (h*NCH + c)*MMf*DDim + i;
            g_Sp[idx] = run;
            run += g_Sc[idx];
        }
    }
    if (tid < MMf) {
        float run = 0.f;
        #pragma unroll
        for (int c = 0; c < NCH; c++) {
            int idx = (h*NCH + c)*MMf + tid;
            g_zp[idx] = run;
            run += g_zc[idx];
        }
    }
}

// ============================================================
// Kernel 4: output per chunk.
//   Z[n,m] = zprev[m] + cumsum_{j<=n} kp[j,m];  q' = qp / Z
//   A = tril(Q' Kp^T);  out = Q' @ Sprev + A @ V
// grid (NCH, HH), block 256.  dynamic smem ~129 KB.
// ============================================================
__global__ void k_out(const float* __restrict__ v, float* __restrict__ out) {
    extern __shared__ float sm[];
    float* qs  = sm;                         // [CC][MMf]      8192
    float* kps = qs + CC*MMf;                // [CC][MMf+1]    8256 (padded)
    float* vs  = kps + CC*(MMf+1);           // [CC][DDim]     4096
    float* Ss  = vs + CC*DDim;               // [MMf][DDim]    8192
    float* As  = Ss + MMf*DDim;              // [CC][CC]       4096
    float* zs  = As + CC*CC;                 // [MMf]           128
    const int c = blockIdx.x, h = blockIdx.y, tid = threadIdx.x;

    const float* qb = g_qp + (h*NNS + c*CC)*MMf;
    for (int i = tid; i < CC*MMf; i += 256) qs[i] = qb[i];
    const float* kb = g_kp + (h*NNS + c*CC)*MMf;
    for (int i = tid; i < CC*MMf; i += 256) {
        int n = i >> 7, m = i & 127;
        kps[n*(MMf+1) + m] = kb[i];
    }
    const float* vb = v + (h*NNS + c*CC)*DDim;
    for (int i = tid; i < CC*DDim; i += 256) vs[i] = vb[i];
    const float* Sb = g_Sp + (h*NCH + c)*MMf*DDim;
    for (int i = tid; i < MMf*DDim; i += 256) Ss[i] = Sb[i];
    if (tid < MMf) zs[tid] = g_zp[(h*NCH + c)*MMf + tid];
    __syncthreads();

    // q' = qp / Z (sequential cumsum over n, parallel over m)
    if (tid < MMf) {
        const int m = tid;
        float run = zs[m];
        #pragma unroll 4
        for (int n = 0; n < CC; n++) {
            run += kps[n*(MMf+1) + m];
            qs[n*MMf + m] = qs[n*MMf + m] / run;
        }
    }
    __syncthreads();

    // A[n][j] = sum_m q'[n,m] kp[j,m], masked j<=n
    {
        const int tx = tid & 15;   // j group: 4
        const int ty = tid >> 4;   // n group: 4
        float acc[4][4];
        #pragma unroll
        for (int r = 0; r < 4; r++)
            #pragma unroll
            for (int cc = 0; cc < 4; cc++) acc[r][cc] = 0.f;
        #pragma unroll 4
        for (int m = 0; m < MMf; m++) {
            float a[4], b[4];
            #pragma unroll
            for (int r = 0; r < 4; r++) a[r] = qs[(ty*4+r)*MMf + m];
            #pragma unroll
            for (int cc = 0; cc < 4; cc++) b[cc] = kps[(tx*4+cc)*(MMf+1) + m];
            #pragma unroll
            for (int r = 0; r < 4; r++)
                #pragma unroll
                for (int cc = 0; cc < 4; cc++) acc[r][cc] = fmaf(a[r], b[cc], acc[r][cc]);
        }
        #pragma unroll
        for (int r = 0; r < 4; r++)
            #pragma unroll
            for (int cc = 0; cc < 4; cc++) {
                int n = ty*4 + r, j = tx*4 + cc;
                As[n*CC + j] = (j <= n) ? acc[r][cc] : 0.f;
            }
    }
    __syncthreads();

    // out[n][d] = sum_m q'[n,m] Sprev[m,d] + sum_j A[n,j] v[j,d]
    {
        const int tx = tid & 15;   // d group: 4
        const int ty = tid >> 4;   // n group: 4
        float acc[4][4];
        #pragma unroll
        for (int r = 0; r < 4; r++)
            #pragma unroll
            for (int cc = 0; cc < 4; cc++) acc[r][cc] = 0.f;
        #pragma unroll 4
        for (int m = 0; m < MMf; m++) {
            float a[4], b[4];
            #pragma unroll
            for (int r = 0; r < 4; r++) a[r] = qs[(ty*4+r)*MMf + m];
            #pragma unroll
            for (int cc = 0; cc < 4; cc++) b[cc] = Ss[m*DDim + tx*4 + cc];
            #pragma unroll
            for (int r = 0; r < 4; r++)
                #pragma unroll
                for (int cc = 0; cc < 4; cc++) acc[r][cc] = fmaf(a[r], b[cc], acc[r][cc]);
        }
        #pragma unroll 4
        for (int j = 0; j < CC; j++) {
            float a[4], b[4];
            #pragma unroll
            for (int r = 0; r < 4; r++) a[r] = As[(ty*4+r)*CC + j];
            #pragma unroll
            for (int cc = 0; cc < 4; cc++) b[cc] = vs[j*DDim + tx*4 + cc];
            #pragma unroll
            for (int r = 0; r < 4; r++)
                #pragma unroll
                for (int cc = 0; cc < 4; cc++) acc[r][cc] = fmaf(a[r], b[cc], acc[r][cc]);
        }
        float* ob = out + (h*NNS + c*CC)*DDim;
        #pragma unroll
        for (int r = 0; r < 4; r++)
            #pragma unroll
            for (int cc = 0; cc < 4; cc++)
                ob[(ty*4+r)*DDim + tx*4 + cc] = acc[r][cc];
    }
}

// ============================================================
extern "C" void kernel_launch(void* const* d_in, const int* in_sizes, int n_in,
                              void* d_out, int out_size) {
    const float* q    = (const float*)d_in[0];
    const float* k    = (const float*)d_in[1];
    const float* v    = (const float*)d_in[2];
    const float* proj = (const float*)d_in[3];
    float* out = (float*)d_out;

    const size_t smem1 = (CC*DDim + DDim*MMf) * sizeof(float);              // 48 KB
    const size_t smem2 = (CC*MMf + CC*DDim) * sizeof(float);                // 48 KB
    const size_t smem4 = (CC*MMf + CC*(MMf+1) + CC*DDim + MMf*DDim + CC*CC + MMf) * sizeof(float); // ~129 KB

    cudaFuncSetAttribute(k_feat,     cudaFuncAttributeMaxDynamicSharedMemorySize, (int)smem1);
    cudaFuncSetAttribute(k_chunksum, cudaFuncAttributeMaxDynamicSharedMemorySize, (int)smem2);
    cudaFuncSetAttribute(k_out,      cudaFuncAttributeMaxDynamicSharedMemorySize, (int)smem4);

    k_feat<<<dim3(NCH, HH, 2), 256, smem1>>>(q, k, proj);
    k_chunksum<<<dim3(NCH, HH), 256, smem2>>>(v);
    k_prefix<<<HH, 512>>>();
    k_out<<<dim3(NCH, HH), 256, smem4>>>(v, out);
}

// round 2
// speedup vs baseline: 2.2750x; 2.2750x over previous
#include <cuda_runtime.h>

#define HH 8
#define NNS 1024
#define DDim 64
#define MMf 128
#define CC 64
#define NCH 16   // NNS / CC
#define EPSF 1e-3f
#define NORMF 0.35355339059327373f   // 64^-0.25

// ---- global scratch (static; zero-init flags) ----
__device__ float g_Sc[HH*NCH*MMf*DDim];   // per-chunk K^T V sums (4 MB)
__device__ float g_zc[HH*NCH*MMf];        // per-chunk kp column sums
__device__ int   g_flag[HH*NCH];          // publish flags (zero-init)

// ---- shared memory layout (float offsets) ----
// persistent across phases:
#define OFF_QS   0                  // qp  [64][128]            8192
#define OFF_KPS  8192               // kp  [64][129] padded     8256
#define OFF_VS   16448              // v   [64][64]             4096
// region D (aliased):
#define OFF_D    20544
#define OFF_PS   (OFF_D)            // phase1: proj^T [64][128] 8192
#define OFF_XQ   (OFF_D+8192)       // phase1: q*norm [64][64]  4096
#define OFF_XK   (OFF_D+12288)      // phase1: k*norm [64][64]  4096
#define OFF_SS   (OFF_D)            // phase3+: S_prev [128][64] 8192
#define OFF_AS   (OFF_D+8192)       // phase5+: A [64][65]      4160
#define OFF_OB   (OFF_D+12352)      // phase5+: out2 [64][64]   4096
#define OFF_ZS   (OFF_D+16448)      // z_prev [128]              128
#define SMEM_FLOATS (OFF_D+16576)   // 37120 floats = 148480 B

__global__ void __launch_bounds__(512, 1)
k_fused(const float* __restrict__ q, const float* __restrict__ k,
        const float* __restrict__ v, const float* __restrict__ proj,
        float* __restrict__ out) {
    extern __shared__ float sm[];
    const int c = blockIdx.x, h = blockIdx.y, tid = threadIdx.x;

    float* qs  = sm + OFF_QS;
    float* kps = sm + OFF_KPS;
    float* vs  = sm + OFF_VS;
    float* ps  = sm + OFF_PS;
    float* xq  = sm + OFF_XQ;
    float* xk  = sm + OFF_XK;
    float* Ss  = sm + OFF_SS;
    float* As  = sm + OFF_AS;
    float* ob  = sm + OFF_OB;
    float* zs  = sm + OFF_ZS;

    // ---------- phase 0: loads ----------
    for (int i = tid; i < MMf*DDim; i += 512) {
        int m = i >> 6, d = i & 63;
        ps[d*MMf + m] = proj[i];                 // transposed: ps[d][m]
    }
    const int base = (h*NNS + c*CC)*DDim;
    for (int i = tid; i < CC*DDim; i += 512) {
        xq[i] = q[base + i] * NORMF;
        xk[i] = k[base + i] * NORMF;
        vs[i] = v[base + i];
    }
    __syncthreads();

    // ---------- phase 1: feature maps (warp-specialized) ----------
    // tid<256: qp -> qs ; tid>=256: kp -> kps (stride 129)
    {
        const int t  = tid & 255;
        const int tx = t & 15;       // m: 8 cols each
        const int ty = t >> 4;       // n: 4 rows each
        const float* xs = (tid < 256) ? xq : xk;
        float acc[4][8];
        #pragma unroll
        for (int r = 0; r < 4; r++)
            #pragma unroll
            for (int cc2 = 0; cc2 < 8; cc2++) acc[r][cc2] = 0.f;

        #pragma unroll 4
        for (int d = 0; d < DDim; d++) {
            float a[4];
            #pragma unroll
            for (int r = 0; r < 4; r++) a[r] = xs[(ty*4+r)*DDim + d];
            float4 b0 = *(const float4*)&ps[d*MMf + tx*8];
            float4 b1 = *(const float4*)&ps[d*MMf + tx*8 + 4];
            float b[8] = {b0.x,b0.y,b0.z,b0.w,b1.x,b1.y,b1.z,b1.w};
            #pragma unroll
            for (int r = 0; r < 4; r++)
                #pragma unroll
                for (int cc2 = 0; cc2 < 8; cc2++)
                    acc[r][cc2] = fmaf(a[r], b[cc2], acc[r][cc2]);
        }
        if (tid < 256) {
            #pragma unroll
            for (int r = 0; r < 4; r++)
                #pragma unroll
                for (int cc2 = 0; cc2 < 8; cc2++)
                    qs[(ty*4+r)*MMf + tx*8 + cc2] = fmaxf(acc[r][cc2], 0.f) + EPSF;
        } else {
            #pragma unroll
            for (int r = 0; r < 4; r++)
                #pragma unroll
                for (int cc2 = 0; cc2 < 8; cc2++)
                    kps[(ty*4+r)*129 + tx*8 + cc2] = fmaxf(acc[r][cc2], 0.f) + EPSF;
        }
    }
    __syncthreads();

    // ---------- phase 2: publish S_c = Kp^T V and z_c ----------
    {
        const int tx = tid & 15;     // d: 4 each
        const int ty = tid >> 4;     // m: 4 each (32 groups)
        float acc[4][4];
        #pragma unroll
        for (int r = 0; r < 4; r++)
            #pragma unroll
            for (int cc2 = 0; cc2 < 4; cc2++) acc[r][cc2] = 0.f;

        #pragma unroll 4
        for (int j = 0; j < CC; j++) {
            float a[4];
            #pragma unroll
            for (int r = 0; r < 4; r++) a[r] = kps[j*129 + ty*4 + r];
            float4 b = *(const float4*)&vs[j*DDim + tx*4];
            #pragma unroll
            for (int r = 0; r < 4; r++) {
                acc[r][0] = fmaf(a[r], b.x, acc[r][0]);
                acc[r][1] = fmaf(a[r], b.y, acc[r][1]);
                acc[r][2] = fmaf(a[r], b.z, acc[r][2]);
                acc[r][3] = fmaf(a[r], b.w, acc[r][3]);
            }
        }
        float* Sb = g_Sc + (h*NCH + c)*MMf*DDim;
        #pragma unroll
        for (int r = 0; r < 4; r++) {
            float4 o = {acc[r][0], acc[r][1], acc[r][2], acc[r][3]};
            *(float4*)&Sb[(ty*4+r)*DDim + tx*4] = o;
        }
        if (tid < MMf) {
            float z = 0.f;
            #pragma unroll 8
            for (int j = 0; j < CC; j++) z += kps[j*129 + tid];
            g_zc[(h*NCH + c)*MMf + tid] = z;
        }
    }
    __threadfence();
    __syncthreads();
    if (tid == 0) atomicExch(&g_flag[h*NCH + c], 1);

    // ---------- phase 3: exclusive prefix (consume earlier chunks) ----------
    for (int i = tid; i < MMf*DDim; i += 512) Ss[i] = 0.f;
    if (tid < MMf) zs[tid] = 0.f;
    for (int c2 = 0; c2 < c; c2++) {
        if (tid == 0) {
            while (atomicAdd(&g_flag[h*NCH + c2], 0) == 0) {}
        }
        __syncthreads();
        const float* Sb = g_Sc + (h*NCH + c2)*MMf*DDim;
        for (int i = tid*4; i < MMf*DDim; i += 2048) {
            float4 t = *(const float4*)&Sb[i];
            Ss[i]   += t.x; Ss[i+1] += t.y; Ss[i+2] += t.z; Ss[i+3] += t.w;
        }
        if (tid < MMf) zs[tid] += g_zc[(h*NCH + c2)*MMf + tid];
    }
    __syncthreads();

    // ---------- phase 4: in-chunk cumsum + q' = qp / Z ----------
    if (tid < MMf) {
        float run = zs[tid];
        #pragma unroll
        for (int n = 0; n < CC; n++) {
            run += kps[n*129 + tid];
            qs[n*MMf + tid] = __fdividef(qs[n*MMf + tid], run);
        }
    }
    __syncthreads();

    // ---------- phase 5: warp-specialized GEMMs ----------
    if (tid < 256) {
        // A = tril(Q' Kp^T)   [64][64], K = 128
        const int tx = tid & 15;   // j: 4 each
        const int ty = tid >> 4;   // n: 4 each
        float acc[4][4];
        #pragma unroll
        for (int r = 0; r < 4; r++)
            #pragma unroll
            for (int cc2 = 0; cc2 < 4; cc2++) acc[r][cc2] = 0.f;
        #pragma unroll 4
        for (int m = 0; m < MMf; m++) {
            float a[4], b[4];
            #pragma unroll
            for (int r = 0; r < 4; r++) a[r] = qs[(ty*4+r)*MMf + m];
            #pragma unroll
            for (int cc2 = 0; cc2 < 4; cc2++) b[cc2] = kps[(tx*4+cc2)*129 + m];
            #pragma unroll
            for (int r = 0; r < 4; r++)
                #pragma unroll
                for (int cc2 = 0; cc2 < 4; cc2++)
                    acc[r][cc2] = fmaf(a[r], b[cc2], acc[r][cc2]);
        }
        #pragma unroll
        for (int r = 0; r < 4; r++)
            #pragma unroll
            for (int cc2 = 0; cc2 < 4; cc2++) {
                int n = ty*4 + r, j = tx*4 + cc2;
                As[n*65 + j] = (j <= n) ? acc[r][cc2] : 0.f;
            }
    } else {
        // out2 = Q' @ S_prev   [64][64], K = 128
        const int t  = tid - 256;
        const int tx = t & 15;     // d: 4 each
        const int ty = t >> 4;     // n: 4 each
        float acc[4][4];
        #pragma unroll
        for (int r = 0; r < 4; r++)
            #pragma unroll
            for (int cc2 = 0; cc2 < 4; cc2++) acc[r][cc2] = 0.f;
        #pragma unroll 4
        for (int m = 0; m < MMf; m++) {
            float a[4];
            #pragma unroll
            for (int r = 0; r < 4; r++) a[r] = qs[(ty*4+r)*MMf + m];
            float4 b = *(const float4*)&Ss[m*DDim + tx*4];
            #pragma unroll
            for (int r = 0; r < 4; r++) {
                acc[r][0] = fmaf(a[r], b.x, acc[r][0]);
                acc[r][1] = fmaf(a[r], b.y, acc[r][1]);
                acc[r][2] = fmaf(a[r], b.z, acc[r][2]);
                acc[r][3] = fmaf(a[r], b.w, acc[r][3]);
            }
        }
        #pragma unroll
        for (int r = 0; r < 4; r++) {
            float4 o = {acc[r][0], acc[r][1], acc[r][2], acc[r][3]};
            *(float4*)&ob[(ty*4+r)*DDim + tx*4] = o;
        }
    }
    __syncthreads();

    // ---------- phase 6: out = A @ V + out2 ----------
    {
        const int tx = tid & 15;   // d: 4 each
        const int ty = tid >> 4;   // n: 2 each (32 groups)
        float acc[2][4];
        #pragma unroll
        for (int r = 0; r < 2; r++)
            #pragma unroll
            for (int cc2 = 0; cc2 < 4; cc2++) acc[r][cc2] = 0.f;
        #pragma unroll 4
        for (int j = 0; j < CC; j++) {
            float a[2];
            #pragma unroll
            for (int r = 0; r < 2; r++) a[r] = As[(ty*2+r)*65 + j];
            float4 b = *(const float4*)&vs[j*DDim + tx*4];
            #pragma unroll
            for (int r = 0; r < 2; r++) {
                acc[r][0] = fmaf(a[r], b.x, acc[r][0]);
                acc[r][1] = fmaf(a[r], b.y, acc[r][1]);
                acc[r][2] = fmaf(a[r], b.z, acc[r][2]);
                acc[r][3] = fmaf(a[r], b.w, acc[r][3]);
            }
        }
        #pragma unroll
        for (int r = 0; r < 2; r++) {
            float4 o2 = *(const float4*)&ob[(ty*2+r)*DDim + tx*4];
            float4 o  = {acc[r][0] + o2.x, acc[r][1] + o2.y,
                         acc[r][2] + o2.z, acc[r][3] + o2.w};
            *(float4*)&out[base + (ty*2+r)*DDim + tx*4] = o;
        }
    }
}

// ============================================================
extern "C" void kernel_launch(void* const* d_in, const int* in_sizes, int n_in,
                              void* d_out, int out_size) {
    const float* q    = (const float*)d_in[0];
    const float* k    = (const float*)d_in[1];
    const float* v    = (const float*)d_in[2];
    const float* proj = (const float*)d_in[3];
    float* out = (float*)d_out;

    const size_t smem = SMEM_FLOATS * sizeof(float);   // 148480 B
    cudaFuncSetAttribute(k_fused, cudaFuncAttributeMaxDynamicSharedMemorySize, (int)smem);
    k_fused<<<dim3(NCH, HH), 512, smem>>>(q, k, v, proj, out);
}

// round 3
// speedup vs baseline: 2.6252x; 1.1539x over previous
#include <cuda_runtime.h>

typedef unsigned long long u64;

#define HH 8
#define NNS 1024
#define DD 64
#define MM 128
#define CC 64
#define NCH 16
#define EPSF 1e-3f
#define NORMF 0.35355339059327373f   // 64^-0.25

// ---- global scratch ----
__device__ float g_Sc[HH*NCH*MM*DD];   // per-chunk Kp^T V  (4 MB)
__device__ float g_zc[HH*NCH*MM];      // per-chunk kp column sums
__device__ int   g_flag[HH*NCH];       // publish flags (zero-init; deterministic re-publish)

// ---- smem layout (float offsets) ----
#define OFF_QS   0                    // qp  [64][130]          8320
#define OFF_KPT  8320                 // kpT [128][68]          8704  -> 17024
#define OFF_VS   17024                // v   [64][64]           4096  -> 21120
#define OFF_D    21120
#define OFF_PS   (OFF_D)              // ph1: projT [64][130]   8320
#define OFF_XQ   (OFF_D+8320)         // ph1: q*norm [64][66]   4224
#define OFF_XKT  (OFF_D+12544)        // ph1: kT*norm [64][68]  4352 -> +16896
#define OFF_SS   (OFF_D)              // ph3+: S_prev [128][64] 8192
#define OFF_AS   (OFF_D+8320)         // ph5+: A [64][68]       4352 -> +12672
#define OFF_OB   (OFF_D+12672)        // ph5+: out2 [64][64]    4096 -> +16768
#define OFF_ZS   (OFF_D+16896)        // z_prev [128]
#define OFF_SEG  (OFF_D+17024)        // seg sums [4][128]       512 -> +17536
#define SMEMF    (OFF_D+17536)        // 38656 floats = 154624 B

// ---- packed f32x2 helpers ----
__device__ __forceinline__ u64 pk2(float x, float y) {
    u64 r; asm("mov.b64 %0,{%1,%2};" : "=l"(r) : "f"(x), "f"(y)); return r;
}
__device__ __forceinline__ u64 dup2(float x) {
    u64 r; asm("mov.b64 %0,{%1,%1};" : "=l"(r) : "f"(x)); return r;
}
__device__ __forceinline__ void upk2(u64 v, float& x, float& y) {
    asm("mov.b64 {%0,%1},%2;" : "=f"(x), "=f"(y) : "l"(v));
}
__device__ __forceinline__ void fma2(u64& d, u64 a, u64 b) {
    asm("fma.rn.f32x2 %0,%1,%2,%0;" : "+l"(d) : "l"(a), "l"(b));
}
__device__ __forceinline__ void add2(u64& d, u64 a) {
    asm("add.rn.f32x2 %0,%0,%1;" : "+l"(d) : "l"(a));
}

__global__ void __launch_bounds__(512, 1)
k_fused(const float* __restrict__ q, const float* __restrict__ k,
        const float* __restrict__ v, const float* __restrict__ proj,
        float* __restrict__ out) {
    extern __shared__ float sm[];
    const int c = blockIdx.x, h = blockIdx.y, tid = threadIdx.x;

    float* qs  = sm + OFF_QS;
    float* kpT = sm + OFF_KPT;
    float* vs  = sm + OFF_VS;
    float* ps  = sm + OFF_PS;
    float* xq  = sm + OFF_XQ;
    float* xkT = sm + OFF_XKT;
    float* Ss  = sm + OFF_SS;
    float* As  = sm + OFF_AS;
    float* ob  = sm + OFF_OB;
    float* zs  = sm + OFF_ZS;
    float* seg = sm + OFF_SEG;

    const int base = (h*NNS + c*CC)*DD;

    // ================= phase 0: loads (all coalesced reads) =================
    for (int i = tid; i < MM*DD; i += 512) {          // proj[m][d] -> ps[d][m]
        int m = i >> 6, d = i & 63;
        ps[d*130 + m] = proj[i];
    }
    for (int i = tid; i < CC*DD; i += 512) {
        int n = i >> 6, d = i & 63;
        float qv = q[base + i] * NORMF;
        float kv = k[base + i] * NORMF;
        xq[n*66 + d]  = qv;
        xkT[d*68 + n] = kv;                           // transposed k
        vs[i] = v[base + i];
    }
    __syncthreads();

    // ============ phase 1: feature maps (warp-specialized halves) ============
    if (tid < 256) {
        // qp[n][m] = relu( xq[n][:] . ps[:][m] ) + eps   -> qs [64][130]
        const int tx = tid & 15;      // m octet
        const int ty = tid >> 4;      // n quad
        u64 acc[4][4];
        #pragma unroll
        for (int r = 0; r < 4; r++)
            #pragma unroll
            for (int p = 0; p < 4; p++) acc[r][p] = 0ull;
        #pragma unroll 4
        for (int d = 0; d < DD; d++) {
            u64 ad[4], b[4];
            #pragma unroll
            for (int r = 0; r < 4; r++) ad[r] = dup2(xq[(4*ty+r)*66 + d]);
            #pragma unroll
            for (int p = 0; p < 4; p++) b[p] = *(const u64*)&ps[d*130 + 8*tx + 2*p];
            #pragma unroll
            for (int r = 0; r < 4; r++)
                #pragma unroll
                for (int p = 0; p < 4; p++) fma2(acc[r][p], ad[r], b[p]);
        }
        #pragma unroll
        for (int r = 0; r < 4; r++)
            #pragma unroll
            for (int p = 0; p < 4; p++) {
                float lo, hi; upk2(acc[r][p], lo, hi);
                lo = fmaxf(lo, 0.f) + EPSF; hi = fmaxf(hi, 0.f) + EPSF;
                *(u64*)&qs[(4*ty+r)*130 + 8*tx + 2*p] = pk2(lo, hi);
            }
    } else {
        // kpT[m][n] = relu( ps[:][m] . xkT[:][n] ) + eps  -> kpT [128][68]
        const int t = tid - 256;
        const int tx = t & 15;        // n quad (2 pairs)
        const int ty = t >> 4;        // m octet
        u64 acc[8][2];
        #pragma unroll
        for (int r = 0; r < 8; r++) { acc[r][0] = 0ull; acc[r][1] = 0ull; }
        #pragma unroll 4
        for (int d = 0; d < DD; d++) {
            ulonglong2 bb = *(const ulonglong2*)&xkT[d*68 + 4*tx];
            #pragma unroll
            for (int r = 0; r < 8; r++) {
                u64 ad = dup2(ps[d*130 + 8*ty + r]);
                fma2(acc[r][0], ad, bb.x);
                fma2(acc[r][1], ad, bb.y);
            }
        }
        #pragma unroll
        for (int r = 0; r < 8; r++) {
            float l0,h0,l1,h1;
            upk2(acc[r][0], l0, h0); upk2(acc[r][1], l1, h1);
            l0 = fmaxf(l0,0.f)+EPSF; h0 = fmaxf(h0,0.f)+EPSF;
            l1 = fmaxf(l1,0.f)+EPSF; h1 = fmaxf(h1,0.f)+EPSF;
            ulonglong2 o; o.x = pk2(l0,h0); o.y = pk2(l1,h1);
            *(ulonglong2*)&kpT[(8*ty+r)*68 + 4*tx] = o;
        }
    }
    __syncthreads();

    // ======== phase 2: publish S_c = Kp^T V  [128m][64d]  and z_c ========
    {
        const int tx = tid & 7;       // d octet (4 pairs)
        const int ty = tid >> 3;      // m pair
        u64 acc[2][4];
        #pragma unroll
        for (int r = 0; r < 2; r++)
            #pragma unroll
            for (int p = 0; p < 4; p++) acc[r][p] = 0ull;
        #pragma unroll 4
        for (int j = 0; j < CC; j++) {
            ulonglong2 b01 = *(const ulonglong2*)&vs[j*64 + 8*tx];
            ulonglong2 b23 = *(const ulonglong2*)&vs[j*64 + 8*tx + 4];
            #pragma unroll
            for (int r = 0; r < 2; r++) {
                u64 ad = dup2(kpT[(2*ty+r)*68 + j]);
                fma2(acc[r][0], ad, b01.x);
                fma2(acc[r][1], ad, b01.y);
                fma2(acc[r][2], ad, b23.x);
                fma2(acc[r][3], ad, b23.y);
            }
        }
        float* Sb = g_Sc + ((h*NCH + c) << 13);
        #pragma unroll
        for (int r = 0; r < 2; r++) {
            ulonglong2 o0; o0.x = acc[r][0]; o0.y = acc[r][1];
            ulonglong2 o1; o1.x = acc[r][2]; o1.y = acc[r][3];
            *(ulonglong2*)&Sb[(2*ty+r)*64 + 8*tx]     = o0;
            *(ulonglong2*)&Sb[(2*ty+r)*64 + 8*tx + 4] = o1;
        }
    }
    {   // segmented column sums of kp (also reused by phase 4)
        const int m = tid & 127, sg = tid >> 7;
        const float* kr = &kpT[m*68 + sg*16];
        float s = 0.f;
        #pragma unroll
        for (int n = 0; n < 16; n++) s += kr[n];
        seg[sg*128 + m] = s;
    }
    __syncthreads();
    if (tid < MM)
        g_zc[(h*NCH + c)*MM + tid] =
            seg[tid] + seg[128 + tid] + seg[256 + tid] + seg[384 + tid];
    __threadfence();
    __syncthreads();
    if (tid == 0) atomicExch(&g_flag[h*NCH + c], 1);

    // ========== phase 3: exclusive prefix over earlier chunks ==========
    if (tid < c) {
        while (atomicAdd(&g_flag[h*NCH + tid], 0) == 0) {}
    }
    __syncthreads();
    __threadfence();
    {
        const int i0 = tid * 16;     // 16 floats per thread of Ss[128][64]
        float4 a0 = {0,0,0,0}, a1 = {0,0,0,0}, a2 = {0,0,0,0}, a3 = {0,0,0,0};
        for (int c2 = 0; c2 < c; c2++) {
            const float4* p = (const float4*)(g_Sc + ((h*NCH + c2) << 13) + i0);
            float4 t0 = p[0], t1 = p[1], t2 = p[2], t3 = p[3];
            a0.x += t0.x; a0.y += t0.y; a0.z += t0.z; a0.w += t0.w;
            a1.x += t1.x; a1.y += t1.y; a1.z += t1.z; a1.w += t1.w;
            a2.x += t2.x; a2.y += t2.y; a2.z += t2.z; a2.w += t2.w;
            a3.x += t3.x; a3.y += t3.y; a3.z += t3.z; a3.w += t3.w;
        }
        float4* d = (float4*)&Ss[i0];
        d[0] = a0; d[1] = a1; d[2] = a2; d[3] = a3;
        if (tid < MM) {
            float z = 0.f;
            for (int c2 = 0; c2 < c; c2++) z += g_zc[(h*NCH + c2)*MM + tid];
            zs[tid] = z;
        }
    }
    __syncthreads();

    // ===== phase 4: segmented cumsum + q' = qp / Z (seg sums from ph2) =====
    {
        const int m = tid & 127, sg = tid >> 7;
        float run = zs[m];
        #pragma unroll
        for (int s = 0; s < 3; s++) if (s < sg) run += seg[s*128 + m];
        const float* kr = &kpT[m*68 + sg*16];
        #pragma unroll
        for (int n = 0; n < 16; n++) {
            run += kr[n];
            const int row = sg*16 + n;
            qs[row*130 + m] = __fdividef(qs[row*130 + m], run);
        }
    }
    __syncthreads();

    // ============ phase 5: warp-specialized GEMMs (K = 128) ============
    if (tid < 256) {
        // A = tril(Q' Kp^T)  [64n][64j]
        const int tx = tid & 15;     // j quad (2 pairs)
        const int ty = tid >> 4;     // n quad
        u64 acc[4][2];
        #pragma unroll
        for (int r = 0; r < 4; r++) { acc[r][0] = 0ull; acc[r][1] = 0ull; }
        #pragma unroll 4
        for (int m = 0; m < MM; m++) {
            ulonglong2 b = *(const ulonglong2*)&kpT[m*68 + 4*tx];
            #pragma unroll
            for (int r = 0; r < 4; r++) {
                u64 ad = dup2(qs[(4*ty+r)*130 + m]);
                fma2(acc[r][0], ad, b.x);
                fma2(acc[r][1], ad, b.y);
            }
        }
        #pragma unroll
        for (int r = 0; r < 4; r++) {
            const int n = 4*ty + r;
            float f0,f1,f2,f3;
            upk2(acc[r][0], f0, f1); upk2(acc[r][1], f2, f3);
            const int j0 = 4*tx;
            As[n*68 + j0]     = (j0   <= n) ? f0 : 0.f;
            As[n*68 + j0 + 1] = (j0+1 <= n) ? f1 : 0.f;
            As[n*68 + j0 + 2] = (j0+2 <= n) ? f2 : 0.f;
            As[n*68 + j0 + 3] = (j0+3 <= n) ? f3 : 0.f;
        }
    } else {
        // out2 = Q' @ S_prev  [64n][64d]
        const int t = tid - 256;
        const int tx = t & 15;       // d quad (2 pairs)
        const int ty = t >> 4;       // n quad
        u64 acc[4][2];
        #pragma unroll
        for (int r = 0; r < 4; r++) { acc[r][0] = 0ull; acc[r][1] = 0ull; }
        #pragma unroll 4
        for (int m = 0; m < MM; m++) {
            ulonglong2 b = *(const ulonglong2*)&Ss[m*64 + 4*tx];
            #pragma unroll
            for (int r = 0; r < 4; r++) {
                u64 ad = dup2(qs[(4*ty+r)*130 + m]);
                fma2(acc[r][0], ad, b.x);
                fma2(acc[r][1], ad, b.y);
            }
        }
        #pragma unroll
        for (int r = 0; r < 4; r++) {
            ulonglong2 o; o.x = acc[r][0]; o.y = acc[r][1];
            *(ulonglong2*)&ob[(4*ty+r)*64 + 4*tx] = o;
        }
    }
    __syncthreads();

    // ============ phase 6: out = A @ V + out2 ============
    {
        const int tx = tid & 15;     // d quad (2 pairs)
        const int ty = tid >> 4;     // n pair
        u64 acc[2][2];
        #pragma unroll
        for (int r = 0; r < 2; r++) { acc[r][0] = 0ull; acc[r][1] = 0ull; }
        #pragma unroll 4
        for (int j = 0; j < CC; j++) {
            ulonglong2 b = *(const ulonglong2*)&vs[j*64 + 4*tx];
            #pragma unroll
            for (int r = 0; r < 2; r++) {
                u64 ad = dup2(As[(2*ty+r)*68 + j]);
                fma2(acc[r][0], ad, b.x);
                fma2(acc[r][1], ad, b.y);
            }
        }
        #pragma unroll
        for (int r = 0; r < 2; r++) {
            ulonglong2 o2 = *(const ulonglong2*)&ob[(2*ty+r)*64 + 4*tx];
            add2(acc[r][0], o2.x);
            add2(acc[r][1], o2.y);
            ulonglong2 o; o.x = acc[r][0]; o.y = acc[r][1];
            *(ulonglong2*)&out[base + (2*ty+r)*64 + 4*tx] = o;
        }
    }
}

// ============================================================
extern "C" void kernel_launch(void* const* d_in, const int* in_sizes, int n_in,
                              void* d_out, int out_size) {
    const float* q    = (const float*)d_in[0];
    const float* k    = (const float*)d_in[1];
    const float* v    = (const float*)d_in[2];
    const float* proj = (const float*)d_in[3];
    float* out = (float*)d_out;

    const size_t smem = SMEMF * sizeof(float);   // 154624 B
    cudaFuncSetAttribute(k_fused, cudaFuncAttributeMaxDynamicSharedMemorySize, (int)smem);
    k_fused<<<dim3(NCH, HH), 512, smem>>>(q, k, v, proj, out);
}

// round 4
// speedup vs baseline: 2.8971x; 1.1036x over previous
#include <cuda_runtime.h>

typedef unsigned long long u64;

#define HH 8
#define NNS 1024
#define DD 64
#define MM 128
#define CC 64
#define NCH 16
#define EPSF 1e-3f
#define NORMF 0.35355339059327373f   // 64^-0.25

// ---- global scratch ----
__device__ float g_Sc[HH*NCH*MM*DD];   // per-chunk Kp^T V  (4 MB)
__device__ float g_zc[HH*NCH*MM];      // per-chunk kp column sums
__device__ int   g_flag[HH*NCH];       // publish flags (zero-init; deterministic re-publish)

// ---- smem layout (float offsets) ----
#define OFF_QST  0                    // qpT [128][68]          8704
#define OFF_KPT  8704                 // kpT [128][68]          8704 -> 17408
#define OFF_VS   17408                // v   [64][64]           4096 -> 21504
#define OFF_D    21504
// phase1 view:
#define OFF_PS   (OFF_D)              // projT [64][132]        8448
#define OFF_XQT  (OFF_D+8448)         // qT*norm [64][68]       4352
#define OFF_XKT  (OFF_D+12800)        // kT*norm [64][68]       4352 -> +17152
// phase3+ view:
#define OFF_SS   (OFF_D)              // S_prev [128][64]       8192
#define OFF_AS   (OFF_D+8192)         // A [64][68]             4352 -> +12544
#define OFF_OB   (OFF_D+12544)        // out2 [64][64]          4096 -> +16640
#define OFF_ZS   (OFF_D+16640)        // z_prev [128]            128 -> +16768
#define OFF_SEG  (OFF_D+16768)        // seg sums [4][128]       512 -> +17280
#define SMEMF    (OFF_D+17280)        // 38784 floats = 155136 B

// ---- packed f32x2 helpers ----
__device__ __forceinline__ u64 pk2(float x, float y) {
    u64 r; asm("mov.b64 %0,{%1,%2};" : "=l"(r) : "f"(x), "f"(y)); return r;
}
__device__ __forceinline__ u64 dup2(float x) {
    u64 r; asm("mov.b64 %0,{%1,%1};" : "=l"(r) : "f"(x)); return r;
}
__device__ __forceinline__ void upk2(u64 v, float& x, float& y) {
    asm("mov.b64 {%0,%1},%2;" : "=f"(x), "=f"(y) : "l"(v));
}
__device__ __forceinline__ void fma2(u64& d, u64 a, u64 b) {
    asm("fma.rn.f32x2 %0,%1,%2,%0;" : "+l"(d) : "l"(a), "l"(b));
}
__device__ __forceinline__ void add2(u64& d, u64 a) {
    asm("add.rn.f32x2 %0,%0,%1;" : "+l"(d) : "l"(a));
}

__global__ void __launch_bounds__(512, 1)
k_fused(const float* __restrict__ q, const float* __restrict__ k,
        const float* __restrict__ v, const float* __restrict__ proj,
        float* __restrict__ out) {
    extern __shared__ float sm[];
    const int c = blockIdx.x, h = blockIdx.y, tid = threadIdx.x;

    float* qsT = sm + OFF_QST;
    float* kpT = sm + OFF_KPT;
    float* vs  = sm + OFF_VS;
    float* ps  = sm + OFF_PS;
    float* xqT = sm + OFF_XQT;
    float* xkT = sm + OFF_XKT;
    float* Ss  = sm + OFF_SS;
    float* As  = sm + OFF_AS;
    float* ob  = sm + OFF_OB;
    float* zs  = sm + OFF_ZS;
    float* seg = sm + OFF_SEG;

    const int base = (h*NNS + c*CC)*DD;

    // ================= phase 0: loads (coalesced reads) =================
    for (int i = tid; i < MM*DD; i += 512) {          // proj[m][d] -> ps[d][m]
        int m = i >> 6, d = i & 63;
        ps[d*132 + m] = proj[i];
    }
    for (int i = tid; i < CC*DD; i += 512) {
        int n = i >> 6, d = i & 63;
        xqT[d*68 + n] = q[base + i] * NORMF;          // transposed inputs
        xkT[d*68 + n] = k[base + i] * NORMF;
        vs[i] = v[base + i];
    }
    __syncthreads();

    // ===== phase 1: featT[m][n] = relu( ps[:,m] . xT[:,n] ) + eps =====
    {
        const float* xT = (tid < 256) ? xqT : xkT;
        float* oT       = (tid < 256) ? qsT : kpT;
        const int t  = tid & 255;
        const int tx = t & 15;        // n quad
        const int ty = t >> 4;        // m octet
        u64 acc[8][2];
        #pragma unroll
        for (int r = 0; r < 8; r++) { acc[r][0] = 0ull; acc[r][1] = 0ull; }
        #pragma unroll 4
        for (int d = 0; d < DD; d++) {
            float4 a0 = *(const float4*)&ps[d*132 + 8*ty];
            float4 a1 = *(const float4*)&ps[d*132 + 8*ty + 4];
            ulonglong2 bb = *(const ulonglong2*)&xT[d*68 + 4*tx];
            float af[8] = {a0.x,a0.y,a0.z,a0.w,a1.x,a1.y,a1.z,a1.w};
            #pragma unroll
            for (int r = 0; r < 8; r++) {
                u64 ad = dup2(af[r]);
                fma2(acc[r][0], ad, bb.x);
                fma2(acc[r][1], ad, bb.y);
            }
        }
        #pragma unroll
        for (int r = 0; r < 8; r++) {
            float l0,h0,l1,h1;
            upk2(acc[r][0], l0, h0); upk2(acc[r][1], l1, h1);
            l0 = fmaxf(l0,0.f)+EPSF; h0 = fmaxf(h0,0.f)+EPSF;
            l1 = fmaxf(l1,0.f)+EPSF; h1 = fmaxf(h1,0.f)+EPSF;
            ulonglong2 o; o.x = pk2(l0,h0); o.y = pk2(l1,h1);
            *(ulonglong2*)&oT[(8*ty+r)*68 + 4*tx] = o;
        }
    }
    __syncthreads();

    // ======== phase 2: publish S_c = Kp^T V  [128m][64d] and z_c ========
    {
        const int tx = tid & 7;       // d octet (4 u64)
        const int ty = tid >> 3;      // m pair
        u64 acc[2][4];
        #pragma unroll
        for (int r = 0; r < 2; r++)
            #pragma unroll
            for (int p = 0; p < 4; p++) acc[r][p] = 0ull;
        #pragma unroll 4
        for (int n = 0; n < CC; n += 4) {
            float4 a0 = *(const float4*)&kpT[(2*ty)*68 + n];
            float4 a1 = *(const float4*)&kpT[(2*ty+1)*68 + n];
            float a0f[4] = {a0.x,a0.y,a0.z,a0.w};
            float a1f[4] = {a1.x,a1.y,a1.z,a1.w};
            #pragma unroll
            for (int jj = 0; jj < 4; jj++) {
                ulonglong2 b0 = *(const ulonglong2*)&vs[(n+jj)*64 + 8*tx];
                ulonglong2 b1 = *(const ulonglong2*)&vs[(n+jj)*64 + 8*tx + 4];
                u64 ad0 = dup2(a0f[jj]), ad1 = dup2(a1f[jj]);
                fma2(acc[0][0], ad0, b0.x); fma2(acc[0][1], ad0, b0.y);
                fma2(acc[0][2], ad0, b1.x); fma2(acc[0][3], ad0, b1.y);
                fma2(acc[1][0], ad1, b0.x); fma2(acc[1][1], ad1, b0.y);
                fma2(acc[1][2], ad1, b1.x); fma2(acc[1][3], ad1, b1.y);
            }
        }
        float* Sb = g_Sc + ((h*NCH + c) << 13);
        #pragma unroll
        for (int r = 0; r < 2; r++) {
            ulonglong2 o0; o0.x = acc[r][0]; o0.y = acc[r][1];
            ulonglong2 o1; o1.x = acc[r][2]; o1.y = acc[r][3];
            *(ulonglong2*)&Sb[(2*ty+r)*64 + 8*tx]     = o0;
            *(ulonglong2*)&Sb[(2*ty+r)*64 + 8*tx + 4] = o1;
        }
    }
    {   // segmented row sums of kpT (reused by phase 4)
        const int m = tid & 127, sg = tid >> 7;
        const float* kr = &kpT[m*68 + sg*16];
        float s = 0.f;
        #pragma unroll
        for (int n = 0; n < 16; n++) s += kr[n];
        seg[sg*128 + m] = s;
    }
    __syncthreads();
    if (tid < MM)
        g_zc[(h*NCH + c)*MM + tid] =
            seg[tid] + seg[128 + tid] + seg[256 + tid] + seg[384 + tid];
    __threadfence();
    __syncthreads();
    if (tid == 0) atomicExch(&g_flag[h*NCH + c], 1);

    // ========== phase 3: exclusive prefix over earlier chunks ==========
    if (tid < c) {
        while (atomicAdd(&g_flag[h*NCH + tid], 0) == 0) {}
    }
    __syncthreads();
    __threadfence();
    {
        const int i0 = tid * 16;
        float4 a0 = {0,0,0,0}, a1 = {0,0,0,0}, a2 = {0,0,0,0}, a3 = {0,0,0,0};
        for (int c2 = 0; c2 < c; c2++) {
            const float4* p = (const float4*)(g_Sc + ((h*NCH + c2) << 13) + i0);
            float4 t0 = p[0], t1 = p[1], t2 = p[2], t3 = p[3];
            a0.x += t0.x; a0.y += t0.y; a0.z += t0.z; a0.w += t0.w;
            a1.x += t1.x; a1.y += t1.y; a1.z += t1.z; a1.w += t1.w;
            a2.x += t2.x; a2.y += t2.y; a2.z += t2.z; a2.w += t2.w;
            a3.x += t3.x; a3.y += t3.y; a3.z += t3.z; a3.w += t3.w;
        }
        float4* d = (float4*)&Ss[i0];
        d[0] = a0; d[1] = a1; d[2] = a2; d[3] = a3;
        if (tid < MM) {
            float z = 0.f;
            for (int c2 = 0; c2 < c; c2++) z += g_zc[(h*NCH + c2)*MM + tid];
            zs[tid] = z;
        }
    }
    __syncthreads();

    // ===== phase 4: segmented cumsum + q' = qp / Z (contiguous rows) =====
    {
        const int m = tid & 127, sg = tid >> 7;
        float run = zs[m];
        #pragma unroll
        for (int s = 0; s < 3; s++) if (s < sg) run += seg[s*128 + m];
        float* kr = &kpT[m*68 + sg*16];
        float* qr = &qsT[m*68 + sg*16];
        #pragma unroll
        for (int n = 0; n < 16; n++) {
            run += kr[n];
            qr[n] = __fdividef(qr[n], run);
        }
    }
    __syncthreads();

    // ============ phase 5: warp-specialized GEMMs (K = 128) ============
    if (tid < 256) {
        // A = tril(Q' Kp^T)  [64n][64j]
        const int tx = tid & 15;     // j quad
        const int ty = tid >> 4;     // n quad
        u64 acc[4][2];
        #pragma unroll
        for (int r = 0; r < 4; r++) { acc[r][0] = 0ull; acc[r][1] = 0ull; }
        #pragma unroll 4
        for (int m = 0; m < MM; m++) {
            float4 a = *(const float4*)&qsT[m*68 + 4*ty];
            ulonglong2 b = *(const ulonglong2*)&kpT[m*68 + 4*tx];
            float af[4] = {a.x,a.y,a.z,a.w};
            #pragma unroll
            for (int r = 0; r < 4; r++) {
                u64 ad = dup2(af[r]);
                fma2(acc[r][0], ad, b.x);
                fma2(acc[r][1], ad, b.y);
            }
        }
        const int j0 = 4*tx;
        #pragma unroll
        for (int r = 0; r < 4; r++) {
            const int n = 4*ty + r;
            float f0,f1,f2,f3;
            upk2(acc[r][0], f0, f1); upk2(acc[r][1], f2, f3);
            float4 o;
            o.x = (j0   <= n) ? f0 : 0.f;
            o.y = (j0+1 <= n) ? f1 : 0.f;
            o.z = (j0+2 <= n) ? f2 : 0.f;
            o.w = (j0+3 <= n) ? f3 : 0.f;
            *(float4*)&As[n*68 + j0] = o;
        }
    } else {
        // out2 = Q' @ S_prev  [64n][64d]
        const int t = tid - 256;
        const int tx = t & 15;       // d quad
        const int ty = t >> 4;       // n quad
        u64 acc[4][2];
        #pragma unroll
        for (int r = 0; r < 4; r++) { acc[r][0] = 0ull; acc[r][1] = 0ull; }
        #pragma unroll 4
        for (int m = 0; m < MM; m++) {
            float4 a = *(const float4*)&qsT[m*68 + 4*ty];
            ulonglong2 b = *(const ulonglong2*)&Ss[m*64 + 4*tx];
            float af[4] = {a.x,a.y,a.z,a.w};
            #pragma unroll
            for (int r = 0; r < 4; r++) {
                u64 ad = dup2(af[r]);
                fma2(acc[r][0], ad, b.x);
                fma2(acc[r][1], ad, b.y);
            }
        }
        #pragma unroll
        for (int r = 0; r < 4; r++) {
            ulonglong2 o; o.x = acc[r][0]; o.y = acc[r][1];
            *(ulonglong2*)&ob[(4*ty+r)*64 + 4*tx] = o;
        }
    }
    __syncthreads();

    // ============ phase 6: out = A @ V + out2 ============
    {
        const int tx = tid & 15;     // d quad
        const int ty = tid >> 4;     // n pair (32 groups)
        u64 acc[2][2];
        #pragma unroll
        for (int r = 0; r < 2; r++) { acc[r][0] = 0ull; acc[r][1] = 0ull; }
        #pragma unroll 4
        for (int j = 0; j < CC; j += 4) {
            float4 a0 = *(const float4*)&As[(2*ty)*68 + j];
            float4 a1 = *(const float4*)&As[(2*ty+1)*68 + j];
            float a0f[4] = {a0.x,a0.y,a0.z,a0.w};
            float a1f[4] = {a1.x,a1.y,a1.z,a1.w};
            #pragma unroll
            for (int jj = 0; jj < 4; jj++) {
                ulonglong2 b = *(const ulonglong2*)&vs[(j+jj)*64 + 4*tx];
                u64 ad0 = dup2(a0f[jj]), ad1 = dup2(a1f[jj]);
                fma2(acc[0][0], ad0, b.x); fma2(acc[0][1], ad0, b.y);
                fma2(acc[1][0], ad1, b.x); fma2(acc[1][1], ad1, b.y);
            }
        }
        #pragma unroll
        for (int r = 0; r < 2; r++) {
            ulonglong2 o2 = *(const ulonglong2*)&ob[(2*ty+r)*64 + 4*tx];
            add2(acc[r][0], o2.x);
            add2(acc[r][1], o2.y);
            ulonglong2 o; o.x = acc[r][0]; o.y = acc[r][1];
            *(ulonglong2*)&out[base + (2*ty+r)*64 + 4*tx] = o;
        }
    }
}

// ============================================================
extern "C" void kernel_launch(void* const* d_in, const int* in_sizes, int n_in,
                              void* d_out, int out_size) {
    const float* q    = (const float*)d_in[0];
    const float* k    = (const float*)d_in[1];
    const float* v    = (const float*)d_in[2];
    const float* proj = (const float*)d_in[3];
    float* out = (float*)d_out;

    const size_t smem = SMEMF * sizeof(float);   // 155136 B
    cudaFuncSetAttribute(k_fused, cudaFuncAttributeMaxDynamicSharedMemorySize, (int)smem);
    k_fused<<<dim3(NCH, HH), 512, smem>>>(q, k, v, proj, out);
}

// round 5
// speedup vs baseline: 3.0679x; 1.0590x over previous
#include <cuda_runtime.h>

typedef unsigned long long u64;

#define HH 8
#define NNS 1024
#define DD 64
#define MM 128
#define CC 64
#define NCH 16
#define EPSF 1e-3f
#define NORMF 0.35355339059327373f   // 64^-0.25

// ---- global scratch ----
__device__ float g_Sc[HH*NCH*MM*DD];   // per-chunk Kp^T V  (4 MB)
__device__ float g_zc[HH*NCH*MM];      // per-chunk kp column sums
__device__ int   g_flag[HH*NCH];       // publish flags (zero-init; deterministic re-publish)

// ---- smem layout (float offsets) ----
#define OFF_QST  0                    // qpT [128][68]          8704
#define OFF_KPT  8704                 // kpT [128][68]          8704 -> 17408
#define OFF_VS   17408                // v   [64][64]           4096 -> 21504
#define OFF_D    21504
// phase1 view:
#define OFF_PS   (OFF_D)              // projT [64][132]        8448
#define OFF_XQT  (OFF_D+8448)         // qT*norm [64][68]       4352
#define OFF_XKT  (OFF_D+12800)        // kT*norm [64][68]       4352
// phase3+ view:
#define OFF_SS   (OFF_D)              // S_prev [128][64]       8192
#define OFF_AS   (OFF_D+8192)         // A [64][68]             4352
#define OFF_OB   (OFF_D+12544)        // out2 [64][64]          4096
#define OFF_ZS   (OFF_D+16640)        // z_prev [128]            128
#define OFF_SEG  (OFF_D+16768)        // seg sums [8][128]      1024
#define SMEMF    (OFF_D+17792)        // 39296 floats = 157184 B

// ---- packed f32x2 helpers ----
__device__ __forceinline__ u64 pk2(float x, float y) {
    u64 r; asm("mov.b64 %0,{%1,%2};" : "=l"(r) : "f"(x), "f"(y)); return r;
}
__device__ __forceinline__ u64 dup2(float x) {
    u64 r; asm("mov.b64 %0,{%1,%1};" : "=l"(r) : "f"(x)); return r;
}
__device__ __forceinline__ void upk2(u64 v, float& x, float& y) {
    asm("mov.b64 {%0,%1},%2;" : "=f"(x), "=f"(y) : "l"(v));
}
__device__ __forceinline__ void fma2(u64& d, u64 a, u64 b) {
    asm("fma.rn.f32x2 %0,%1,%2,%0;" : "+l"(d) : "l"(a), "l"(b));
}
__device__ __forceinline__ void add2(u64& d, u64 a) {
    asm("add.rn.f32x2 %0,%0,%1;" : "+l"(d) : "l"(a));
}

__global__ void __launch_bounds__(1024, 1)
k_fused(const float* __restrict__ q, const float* __restrict__ k,
        const float* __restrict__ v, const float* __restrict__ proj,
        float* __restrict__ out) {
    extern __shared__ float sm[];
    const int c = blockIdx.x, h = blockIdx.y, tid = threadIdx.x;

    float* qsT = sm + OFF_QST;
    float* kpT = sm + OFF_KPT;
    float* vs  = sm + OFF_VS;
    float* ps  = sm + OFF_PS;
    float* xqT = sm + OFF_XQT;
    float* xkT = sm + OFF_XKT;
    float* Ss  = sm + OFF_SS;
    float* As  = sm + OFF_AS;
    float* ob  = sm + OFF_OB;
    float* zs  = sm + OFF_ZS;
    float* seg = sm + OFF_SEG;

    const int base = (h*NNS + c*CC)*DD;

    // ================= phase 0: loads =================
    for (int i = tid; i < MM*DD; i += 1024) {          // proj[m][d] -> ps[d][m]
        int m = i >> 6, d = i & 63;
        ps[d*132 + m] = proj[i];
    }
    for (int i = tid; i < CC*DD; i += 1024) {
        int n = i >> 6, d = i & 63;
        xqT[d*68 + n] = q[base + i] * NORMF;           // transposed inputs
        xkT[d*68 + n] = k[base + i] * NORMF;
        vs[i] = v[base + i];
    }
    __syncthreads();

    // ===== phase 1: featT[m][n] = relu( ps[:,m] . xT[:,n] ) + eps =====
    // halves: tid<512 -> qpT, else kpT.  per thread: 8 m x 2 n.
    {
        const float* xT = (tid < 512) ? xqT : xkT;
        float* oT       = (tid < 512) ? qsT : kpT;
        const int t  = tid & 511;
        const int tx = t & 31;        // n pair
        const int ty = t >> 5;        // m octet (16 groups)
        u64 acc[4][2];                // [m-pair p][n]
        #pragma unroll
        for (int p = 0; p < 4; p++) { acc[p][0] = 0ull; acc[p][1] = 0ull; }
        #pragma unroll 4
        for (int d = 0; d < DD; d++) {
            // a: 8 consecutive m-values = 4 packed u64 pairs
            ulonglong2 a01 = *(const ulonglong2*)&ps[d*132 + 8*ty];
            ulonglong2 a23 = *(const ulonglong2*)&ps[d*132 + 8*ty + 4];
            float2 bf = *(const float2*)&xT[d*68 + 2*tx];
            u64 b0 = dup2(bf.x), b1 = dup2(bf.y);
            fma2(acc[0][0], a01.x, b0); fma2(acc[0][1], a01.x, b1);
            fma2(acc[1][0], a01.y, b0); fma2(acc[1][1], a01.y, b1);
            fma2(acc[2][0], a23.x, b0); fma2(acc[2][1], a23.x, b1);
            fma2(acc[3][0], a23.y, b0); fma2(acc[3][1], a23.y, b1);
        }
        #pragma unroll
        for (int p = 0; p < 4; p++)
            #pragma unroll
            for (int nn = 0; nn < 2; nn++) {
                float lo, hi; upk2(acc[p][nn], lo, hi);
                lo = fmaxf(lo, 0.f) + EPSF;
                hi = fmaxf(hi, 0.f) + EPSF;
                const int ncol = 2*tx + nn;
                oT[(8*ty + 2*p)*68 + ncol]     = lo;
                oT[(8*ty + 2*p + 1)*68 + ncol] = hi;
            }
    }
    __syncthreads();

    // ======== phase 2: publish S_c = Kp^T V [128m][64d], z_c ========
    {
        const int tx = tid & 15;      // d quad
        const int ty = tid >> 4;      // m pair (64 groups)
        u64 acc[2][2];
        acc[0][0]=0ull; acc[0][1]=0ull; acc[1][0]=0ull; acc[1][1]=0ull;
        #pragma unroll 4
        for (int n = 0; n < CC; n += 4) {
            float4 a0 = *(const float4*)&kpT[(2*ty)*68 + n];
            float4 a1 = *(const float4*)&kpT[(2*ty+1)*68 + n];
            float a0f[4] = {a0.x,a0.y,a0.z,a0.w};
            float a1f[4] = {a1.x,a1.y,a1.z,a1.w};
            #pragma unroll
            for (int jj = 0; jj < 4; jj++) {
                ulonglong2 b = *(const ulonglong2*)&vs[(n+jj)*64 + 4*tx];
                u64 ad0 = dup2(a0f[jj]), ad1 = dup2(a1f[jj]);
                fma2(acc[0][0], ad0, b.x); fma2(acc[0][1], ad0, b.y);
                fma2(acc[1][0], ad1, b.x); fma2(acc[1][1], ad1, b.y);
            }
        }
        float* Sb = g_Sc + ((h*NCH + c) << 13);
        #pragma unroll
        for (int r = 0; r < 2; r++) {
            ulonglong2 o; o.x = acc[r][0]; o.y = acc[r][1];
            *(ulonglong2*)&Sb[(2*ty+r)*64 + 4*tx] = o;
        }
    }
    {   // segmented row sums of kpT: 8 segments x 8 rows
        const int m = tid & 127, sg = tid >> 7;
        const float* kr = &kpT[m*68 + sg*8];
        float s = 0.f;
        #pragma unroll
        for (int n = 0; n < 8; n++) s += kr[n];
        seg[sg*128 + m] = s;
    }
    __syncthreads();
    if (tid < MM) {
        float z = 0.f;
        #pragma unroll
        for (int s = 0; s < 8; s++) z += seg[s*128 + tid];
        g_zc[(h*NCH + c)*MM + tid] = z;
    }
    __threadfence();
    __syncthreads();
    if (tid == 0) atomicExch(&g_flag[h*NCH + c], 1);

    // ========== phase 3: exclusive prefix over earlier chunks ==========
    if (tid < c) {
        while (atomicAdd(&g_flag[h*NCH + tid], 0) == 0) {}
    }
    __syncthreads();
    __threadfence();
    {
        const int i0 = tid * 8;       // 8 floats per thread of Ss[128][64]
        float4 a0 = {0,0,0,0}, a1 = {0,0,0,0};
        for (int c2 = 0; c2 < c; c2++) {
            const float4* p = (const float4*)(g_Sc + ((h*NCH + c2) << 13) + i0);
            float4 t0 = p[0], t1 = p[1];
            a0.x += t0.x; a0.y += t0.y; a0.z += t0.z; a0.w += t0.w;
            a1.x += t1.x; a1.y += t1.y; a1.z += t1.z; a1.w += t1.w;
        }
        float4* d = (float4*)&Ss[i0];
        d[0] = a0; d[1] = a1;
        if (tid < MM) {
            float z = 0.f;
            for (int c2 = 0; c2 < c; c2++) z += g_zc[(h*NCH + c2)*MM + tid];
            zs[tid] = z;
        }
    }
    __syncthreads();

    // ===== phase 4: segmented cumsum + q' = qp / Z (8-deep chain) =====
    {
        const int m = tid & 127, sg = tid >> 7;
        float run = zs[m];
        #pragma unroll
        for (int s = 0; s < 7; s++) if (s < sg) run += seg[s*128 + m];
        float* kr = &kpT[m*68 + sg*8];
        float* qr = &qsT[m*68 + sg*8];
        #pragma unroll
        for (int n = 0; n < 8; n++) {
            run += kr[n];
            qr[n] = __fdividef(qr[n], run);
        }
    }
    __syncthreads();

    // ============ phase 5: warp-specialized GEMMs (K = 128) ============
    if (tid < 512) {
        // A = tril(Q' Kp^T)  [64n][64j]:  per thread 2 n x 4 j
        const int tx = tid & 15;      // j quad
        const int ty = tid >> 4;      // n pair (32 groups)
        u64 acc[2][2];
        acc[0][0]=0ull; acc[0][1]=0ull; acc[1][0]=0ull; acc[1][1]=0ull;
        #pragma unroll 8
        for (int m = 0; m < MM; m++) {
            float2 a = *(const float2*)&qsT[m*68 + 2*ty];
            ulonglong2 b = *(const ulonglong2*)&kpT[m*68 + 4*tx];
            u64 ad0 = dup2(a.x), ad1 = dup2(a.y);
            fma2(acc[0][0], ad0, b.x); fma2(acc[0][1], ad0, b.y);
            fma2(acc[1][0], ad1, b.x); fma2(acc[1][1], ad1, b.y);
        }
        const int j0 = 4*tx;
        #pragma unroll
        for (int r = 0; r < 2; r++) {
            const int n = 2*ty + r;
            float f0,f1,f2,f3;
            upk2(acc[r][0], f0, f1); upk2(acc[r][1], f2, f3);
            float4 o;
            o.x = (j0   <= n) ? f0 : 0.f;
            o.y = (j0+1 <= n) ? f1 : 0.f;
            o.z = (j0+2 <= n) ? f2 : 0.f;
            o.w = (j0+3 <= n) ? f3 : 0.f;
            *(float4*)&As[n*68 + j0] = o;
        }
    } else {
        // out2 = Q' @ S_prev  [64n][64d]: per thread 2 n x 4 d
        const int t = tid - 512;
        const int tx = t & 15;        // d quad
        const int ty = t >> 4;        // n pair
        u64 acc[2][2];
        acc[0][0]=0ull; acc[0][1]=0ull; acc[1][0]=0ull; acc[1][1]=0ull;
        #pragma unroll 8
        for (int m = 0; m < MM; m++) {
            float2 a = *(const float2*)&qsT[m*68 + 2*ty];
            ulonglong2 b = *(const ulonglong2*)&Ss[m*64 + 4*tx];
            u64 ad0 = dup2(a.x), ad1 = dup2(a.y);
            fma2(acc[0][0], ad0, b.x); fma2(acc[0][1], ad0, b.y);
            fma2(acc[1][0], ad1, b.x); fma2(acc[1][1], ad1, b.y);
        }
        #pragma unroll
        for (int r = 0; r < 2; r++) {
            ulonglong2 o; o.x = acc[r][0]; o.y = acc[r][1];
            *(ulonglong2*)&ob[(2*ty+r)*64 + 4*tx] = o;
        }
    }
    __syncthreads();

    // ============ phase 6: out = A @ V + out2 ============
    {
        const int tx = tid & 15;      // d quad
        const int ty = tid >> 4;      // n (64 groups)
        u64 acc[2];
        acc[0] = 0ull; acc[1] = 0ull;
        #pragma unroll 4
        for (int j = 0; j < CC; j += 4) {
            float4 a = *(const float4*)&As[ty*68 + j];
            float af[4] = {a.x,a.y,a.z,a.w};
            #pragma unroll
            for (int jj = 0; jj < 4; jj++) {
                ulonglong2 b = *(const ulonglong2*)&vs[(j+jj)*64 + 4*tx];
                u64 ad = dup2(af[jj]);
                fma2(acc[0], ad, b.x);
                fma2(acc[1], ad, b.y);
            }
        }
        ulonglong2 o2 = *(const ulonglong2*)&ob[ty*64 + 4*tx];
        add2(acc[0], o2.x);
        add2(acc[1], o2.y);
        ulonglong2 o; o.x = acc[0]; o.y = acc[1];
        *(ulonglong2*)&out[base + ty*64 + 4*tx] = o;
    }
}

// ============================================================
extern "C" void kernel_launch(void* const* d_in, const int* in_sizes, int n_in,
                              void* d_out, int out_size) {
    const float* q    = (const float*)d_in[0];
    const float* k    = (const float*)d_in[1];
    const float* v    = (const float*)d_in[2];
    const float* proj = (const float*)d_in[3];
    float* out = (float*)d_out;

    const size_t smem = SMEMF * sizeof(float);   // 157184 B
    cudaFuncSetAttribute(k_fused, cudaFuncAttributeMaxDynamicSharedMemorySize, (int)smem);
    k_fused<<<dim3(NCH, HH), 1024, smem>>>(q, k, v, proj, out);
}

// round 6
// speedup vs baseline: 3.1721x; 1.0340x over previous
#include <cuda_runtime.h>

typedef unsigned long long u64;

#define HH 8
#define NNS 1024
#define DD 64
#define MM 128
#define CC 64
#define NCH 16
#define EPSF 1e-3f
#define NORMF 0.35355339059327373f   // 64^-0.25

// ---- global scratch ----
__device__ float g_Sc[HH*NCH*MM*DD];   // per-chunk Kp^T V  (4 MB)
__device__ float g_zc[HH*NCH*MM];      // per-chunk kp column sums
__device__ int   g_flag[HH*NCH];       // publish flags (zero-init; deterministic re-publish)

// ---- smem layout (float offsets) ----
// persistent:
#define OFF_QST  0                     // qpT [128][68]        8704
#define OFF_KPT  8704                  // kpT [128][68]        8704 -> 17408
#define OFF_VS   17408                 // v   [64][64]         4096 -> 21504
#define OFF_SEG  21504                 // seg sums [8][128]    1024 -> 22528
#define OFF_ZQ   22528                 // z prefix partials [4][128] 512 -> 23040
#define OFF_D    23040
// phase1 view:
#define OFF_PS   (OFF_D)               // projT [64][132]      8448
#define OFF_XQT  (OFF_D+8448)          // qT*norm [64][68]     4352
#define OFF_XKT  (OFF_D+12800)         // kT*norm [64][68]     4352
// phase2 view:
#define OFF_SB0  (OFF_D)               // S partial lo [128][64] 8192
#define OFF_SB1  (OFF_D+8192)          // S partial hi [128][64] 8192
// phase3+ view:
#define OFF_SS   (OFF_D)               // S_prev [128][64]     8192
#define OFF_AS0  (OFF_D+8192)          // A partial lo [64][68] 4352
#define OFF_AS1  (OFF_D+12544)         // A partial hi [64][68] 4352
#define OFF_OB0  (OFF_D+16896)         // out2 partial lo [64][64] 4096
#define OFF_OB1  (OFF_D+20992)         // out2 partial hi [64][64] 4096
#define SMEMF    (OFF_D+25088)         // 48128 floats = 192512 B

// ---- packed f32x2 helpers ----
__device__ __forceinline__ u64 pk2(float x, float y) {
    u64 r; asm("mov.b64 %0,{%1,%2};" : "=l"(r) : "f"(x), "f"(y)); return r;
}
__device__ __forceinline__ u64 dup2(float x) {
    u64 r; asm("mov.b64 %0,{%1,%1};" : "=l"(r) : "f"(x)); return r;
}
__device__ __forceinline__ void upk2(u64 v, float& x, float& y) {
    asm("mov.b64 {%0,%1},%2;" : "=f"(x), "=f"(y) : "l"(v));
}
__device__ __forceinline__ void fma2(u64& d, u64 a, u64 b) {
    asm("fma.rn.f32x2 %0,%1,%2,%0;" : "+l"(d) : "l"(a), "l"(b));
}
__device__ __forceinline__ void add2(u64& d, u64 a) {
    asm("add.rn.f32x2 %0,%0,%1;" : "+l"(d) : "l"(a));
}

__global__ void __launch_bounds__(1024, 1)
k_fused(const float* __restrict__ q, const float* __restrict__ k,
        const float* __restrict__ v, const float* __restrict__ proj,
        float* __restrict__ out) {
    extern __shared__ float sm[];
    const int c = blockIdx.x, h = blockIdx.y, tid = threadIdx.x;

    float* qsT = sm + OFF_QST;
    float* kpT = sm + OFF_KPT;
    float* vs  = sm + OFF_VS;
    float* seg = sm + OFF_SEG;
    float* zq  = sm + OFF_ZQ;
    float* ps  = sm + OFF_PS;
    float* xqT = sm + OFF_XQT;
    float* xkT = sm + OFF_XKT;
    float* Sb0 = sm + OFF_SB0;
    float* Sb1 = sm + OFF_SB1;
    float* Ss  = sm + OFF_SS;
    float* As0 = sm + OFF_AS0;
    float* As1 = sm + OFF_AS1;
    float* ob0 = sm + OFF_OB0;
    float* ob1 = sm + OFF_OB1;

    const int base = (h*NNS + c*CC)*DD;

    // ================= phase 0: loads =================
    for (int i = tid; i < MM*DD; i += 1024) {          // proj[m][d] -> ps[d][m]
        int m = i >> 6, d = i & 63;
        ps[d*132 + m] = proj[i];
    }
    for (int i = tid; i < CC*DD; i += 1024) {
        int n = i >> 6, d = i & 63;
        xqT[d*68 + n] = q[base + i] * NORMF;
        xkT[d*68 + n] = k[base + i] * NORMF;
        vs[i] = v[base + i];
    }
    __syncthreads();

    // ===== phase 1: featT[m][n] = relu( ps[:,m] . xT[:,n] ) + eps =====
    // halves: tid<512 -> qpT, else kpT.  8m x 2n tiles, 2-stage pipeline.
    {
        const float* xT = (tid < 512) ? xqT : xkT;
        float* oT       = (tid < 512) ? qsT : kpT;
        const int t  = tid & 511;
        const int tx = t & 31;        // n pair
        const int ty = t >> 5;        // m octet
        u64 acc[4][2];
        #pragma unroll
        for (int p = 0; p < 4; p++) { acc[p][0] = 0ull; acc[p][1] = 0ull; }

        const float* pa = &ps[8*ty];
        const float* pb = &xT[2*tx];
        ulonglong2 a01 = *(const ulonglong2*)pa;
        ulonglong2 a23 = *(const ulonglong2*)(pa + 4);
        float2 bf = *(const float2*)pb;
        #pragma unroll 2
        for (int d = 0; d < DD; d++) {
            ulonglong2 na01, na23; float2 nbf;
            if (d < DD-1) {
                na01 = *(const ulonglong2*)(pa + (d+1)*132);
                na23 = *(const ulonglong2*)(pa + (d+1)*132 + 4);
                nbf  = *(const float2*)(pb + (d+1)*68);
            }
            u64 b0 = dup2(bf.x), b1 = dup2(bf.y);
            fma2(acc[0][0], a01.x, b0); fma2(acc[0][1], a01.x, b1);
            fma2(acc[1][0], a01.y, b0); fma2(acc[1][1], a01.y, b1);
            fma2(acc[2][0], a23.x, b0); fma2(acc[2][1], a23.x, b1);
            fma2(acc[3][0], a23.y, b0); fma2(acc[3][1], a23.y, b1);
            a01 = na01; a23 = na23; bf = nbf;
        }
        #pragma unroll
        for (int p = 0; p < 4; p++)
            #pragma unroll
            for (int nn = 0; nn < 2; nn++) {
                float lo, hi; upk2(acc[p][nn], lo, hi);
                lo = fmaxf(lo, 0.f) + EPSF;
                hi = fmaxf(hi, 0.f) + EPSF;
                const int ncol = 2*tx + nn;
                oT[(8*ty + 2*p)*68 + ncol]     = lo;
                oT[(8*ty + 2*p + 1)*68 + ncol] = hi;
            }
    }
    __syncthreads();

    // ======== phase 2: S_c = Kp^T V  (K-split over n, 4m x 4d tiles) ========
    {
        const int g  = tid >> 9;      // n-half
        const int t  = tid & 511;
        const int tx = t & 15;        // d quad
        const int ty = t >> 4;        // m quad (32 groups)
        float* Sb = g ? Sb1 : Sb0;
        const int n0b = g * 32;
        u64 acc[4][2];
        #pragma unroll
        for (int r = 0; r < 4; r++) { acc[r][0] = 0ull; acc[r][1] = 0ull; }
        #pragma unroll 4
        for (int n0 = 0; n0 < 32; n0 += 4) {
            float4 a[4];
            #pragma unroll
            for (int r = 0; r < 4; r++)
                a[r] = *(const float4*)&kpT[(4*ty+r)*68 + n0b + n0];
            #pragma unroll
            for (int jj = 0; jj < 4; jj++) {
                ulonglong2 b = *(const ulonglong2*)&vs[(n0b + n0 + jj)*64 + 4*tx];
                const float aj[4] = {((const float*)&a[0])[jj], ((const float*)&a[1])[jj],
                                     ((const float*)&a[2])[jj], ((const float*)&a[3])[jj]};
                #pragma unroll
                for (int r = 0; r < 4; r++) {
                    u64 ad = dup2(aj[r]);
                    fma2(acc[r][0], ad, b.x);
                    fma2(acc[r][1], ad, b.y);
                }
            }
        }
        #pragma unroll
        for (int r = 0; r < 4; r++) {
            ulonglong2 o; o.x = acc[r][0]; o.y = acc[r][1];
            *(ulonglong2*)&Sb[(4*ty+r)*64 + 4*tx] = o;
        }
    }
    {   // segmented row sums of kpT: 8 segments x 8 rows (persistent seg)
        const int m = tid & 127, sg = tid >> 7;
        const float* kr = &kpT[m*68 + sg*8];
        float s = 0.f;
        #pragma unroll
        for (int n = 0; n < 8; n++) s += kr[n];
        seg[sg*128 + m] = s;
    }
    __syncthreads();
    {   // merge partials -> publish g_Sc ; z_c from seg
        const int i0 = tid * 8;
        float4 p0 = *(const float4*)&Sb0[i0];
        float4 p1 = *(const float4*)&Sb0[i0+4];
        float4 q0 = *(const float4*)&Sb1[i0];
        float4 q1 = *(const float4*)&Sb1[i0+4];
        float4 o0 = {p0.x+q0.x, p0.y+q0.y, p0.z+q0.z, p0.w+q0.w};
        float4 o1 = {p1.x+q1.x, p1.y+q1.y, p1.z+q1.z, p1.w+q1.w};
        float* Sg = g_Sc + ((h*NCH + c) << 13);
        *(float4*)&Sg[i0]   = o0;
        *(float4*)&Sg[i0+4] = o1;
        if (tid < MM) {
            float z = 0.f;
            #pragma unroll
            for (int s = 0; s < 8; s++) z += seg[s*128 + tid];
            g_zc[(h*NCH + c)*MM + tid] = z;
        }
    }
    __threadfence();
    __syncthreads();
    if (tid == 0) atomicExch(&g_flag[h*NCH + c], 1);

    // ========== phase 3/4 overlapped ==========
    if (tid < c) {
        while (atomicAdd(&g_flag[h*NCH + tid], 0) == 0) {}
    }
    __syncthreads();
    __threadfence();
    if (tid < 512) {
        // --- z prefix (4-way) + cumsum + divide ---
        const int m = tid & 127, qtr = tid >> 7;
        float z = 0.f;
        for (int c2 = qtr; c2 < c; c2 += 4)
            z += g_zc[(h*NCH + c2)*MM + m];
        zq[qtr*128 + m] = z;
        asm volatile("bar.sync 1, 512;" ::: "memory");
        // cumsum: 4 segments x 16 rows
        const int sg = qtr;
        float run = zq[m] + zq[128 + m] + zq[256 + m] + zq[384 + m];
        #pragma unroll
        for (int s = 0; s < 3; s++)
            if (s < sg) run += seg[(2*s)*128 + m] + seg[(2*s+1)*128 + m];
        float* kr = &kpT[m*68 + sg*16];
        float* qr = &qsT[m*68 + sg*16];
        #pragma unroll
        for (int n = 0; n < 16; n++) {
            run += kr[n];
            qr[n] = __fdividef(qr[n], run);
        }
    } else {
        // --- S_prev accumulation from L2 ---
        const int i0 = (tid - 512) * 16;
        float4 a0 = {0,0,0,0}, a1 = {0,0,0,0}, a2 = {0,0,0,0}, a3 = {0,0,0,0};
        for (int c2 = 0; c2 < c; c2++) {
            const float4* p = (const float4*)(g_Sc + ((h*NCH + c2) << 13) + i0);
            float4 t0 = p[0], t1 = p[1], t2 = p[2], t3 = p[3];
            a0.x += t0.x; a0.y += t0.y; a0.z += t0.z; a0.w += t0.w;
            a1.x += t1.x; a1.y += t1.y; a1.z += t1.z; a1.w += t1.w;
            a2.x += t2.x; a2.y += t2.y; a2.z += t2.z; a2.w += t2.w;
            a3.x += t3.x; a3.y += t3.y; a3.z += t3.z; a3.w += t3.w;
        }
        float4* d = (float4*)&Ss[i0];
        d[0] = a0; d[1] = a1; d[2] = a2; d[3] = a3;
    }
    __syncthreads();

    // ============ phase 5: 4-way split GEMMs (m-halves, 4n x 4c tiles) ============
    {
        const int g  = tid >> 8;      // 0: A-lo, 1: A-hi, 2: out2-lo, 3: out2-hi
        const int t  = tid & 255;
        const int tx = t & 15;        // j/d quad
        const int ty = t >> 4;        // n quad (16 groups)
        const int m0 = (g & 1) * 64;
        u64 acc[4][2];
        #pragma unroll
        for (int r = 0; r < 4; r++) { acc[r][0] = 0ull; acc[r][1] = 0ull; }
        if (g < 2) {
            // A partial = Q'[:,n] . Kp[:,j] over m-half
            #pragma unroll 4
            for (int mi = 0; mi < 64; mi++) {
                const int m = m0 + mi;
                float4 a = *(const float4*)&qsT[m*68 + 4*ty];
                ulonglong2 b = *(const ulonglong2*)&kpT[m*68 + 4*tx];
                const float af[4] = {a.x, a.y, a.z, a.w};
                #pragma unroll
                for (int r = 0; r < 4; r++) {
                    u64 ad = dup2(af[r]);
                    fma2(acc[r][0], ad, b.x);
                    fma2(acc[r][1], ad, b.y);
                }
            }
            float* As = (g & 1) ? As1 : As0;
            const int j0 = 4*tx;
            #pragma unroll
            for (int r = 0; r < 4; r++) {
                const int n = 4*ty + r;
                float f0,f1,f2,f3;
                upk2(acc[r][0], f0, f1); upk2(acc[r][1], f2, f3);
                float4 o;
                o.x = (j0   <= n) ? f0 : 0.f;
                o.y = (j0+1 <= n) ? f1 : 0.f;
                o.z = (j0+2 <= n) ? f2 : 0.f;
                o.w = (j0+3 <= n) ? f3 : 0.f;
                *(float4*)&As[n*68 + j0] = o;
            }
        } else {
            // out2 partial = Q'[:,n] . S_prev[:,d] over m-half
            #pragma unroll 4
            for (int mi = 0; mi < 64; mi++) {
                const int m = m0 + mi;
                float4 a = *(const float4*)&qsT[m*68 + 4*ty];
                ulonglong2 b = *(const ulonglong2*)&Ss[m*64 + 4*tx];
                const float af[4] = {a.x, a.y, a.z, a.w};
                #pragma unroll
                for (int r = 0; r < 4; r++) {
                    u64 ad = dup2(af[r]);
                    fma2(acc[r][0], ad, b.x);
                    fma2(acc[r][1], ad, b.y);
                }
            }
            float* ob = (g & 1) ? ob1 : ob0;
            #pragma unroll
            for (int r = 0; r < 4; r++) {
                ulonglong2 o; o.x = acc[r][0]; o.y = acc[r][1];
                *(ulonglong2*)&ob[(4*ty+r)*64 + 4*tx] = o;
            }
        }
    }
    __syncthreads();

    // ============ phase 6: out = (A0+A1) @ V + ob0 + ob1 ============
    {
        const int tx = tid & 15;      // d quad
        const int ty = tid >> 4;      // n (64 groups)
        u64 acc[2];
        acc[0] = 0ull; acc[1] = 0ull;
        #pragma unroll 4
        for (int j = 0; j < CC; j += 4) {
            float4 u = *(const float4*)&As0[ty*68 + j];
            float4 w = *(const float4*)&As1[ty*68 + j];
            const float af[4] = {u.x+w.x, u.y+w.y, u.z+w.z, u.w+w.w};
            #pragma unroll
            for (int jj = 0; jj < 4; jj++) {
                ulonglong2 b = *(const ulonglong2*)&vs[(j+jj)*64 + 4*tx];
                u64 ad = dup2(af[jj]);
                fma2(acc[0], ad, b.x);
                fma2(acc[1], ad, b.y);
            }
        }
        ulonglong2 p0 = *(const ulonglong2*)&ob0[ty*64 + 4*tx];
        ulonglong2 p1 = *(const ulonglong2*)&ob1[ty*64 + 4*tx];
        add2(acc[0], p0.x); add2(acc[0], p1.x);
        add2(acc[1], p0.y); add2(acc[1], p1.y);
        ulonglong2 o; o.x = acc[0]; o.y = acc[1];
        *(ulonglong2*)&out[base + ty*64 + 4*tx] = o;
    }
}

// ============================================================
extern "C" void kernel_launch(void* const* d_in, const int* in_sizes, int n_in,
                              void* d_out, int out_size) {
    const float* q    = (const float*)d_in[0];
    const float* k    = (const float*)d_in[1];
    const float* v    = (const float*)d_in[2];
    const float* proj = (const float*)d_in[3];
    float* out = (float*)d_out;

    const size_t smem = SMEMF * sizeof(float);   // 192512 B
    cudaFuncSetAttribute(k_fused, cudaFuncAttributeMaxDynamicSharedMemorySize, (int)smem);
    k_fused<<<dim3(NCH, HH), 1024, smem>>>(q, k, v, proj, out);
}

// round 7
// speedup vs baseline: 4.8479x; 1.5283x over previous
#include <cuda_runtime.h>

typedef unsigned long long u64;
typedef unsigned int uint32;

#define HH 8
#define NNS 1024
#define DD 64
#define MM 128
#define CC 64
#define NCH 16
#define EPSF 1e-3f
#define NORMF 0.35355339059327373f   // 64^-0.25

// ---- global scratch ----
__device__ float g_Sc[HH*NCH*MM*DD];   // per-chunk Kp^T V (fp32, 4 MB)
__device__ float g_zc[HH*NCH*MM];      // per-chunk kp column sums
__device__ int   g_flag[HH*NCH];       // publish flags (zero-init; deterministic re-publish)

// ---- smem layout (float offsets) ----
// persistent:
#define OFF_QST  0                     // qpT [128][72]  (qp[n][m] at [m][n])  9216
#define OFF_KPT  9216                  // kpT [128][72]                        9216 -> 18432
#define OFF_VS   18432                 // v   [64][72]                         4608 -> 23040
#define OFF_SEG  23040                 // seg sums [8][128]                    1024 -> 24064
#define OFF_ZQ   24064                 // z prefix partials [4][128]            512 -> 24576
#define OFF_D    24576
// phase1 view:
#define OFF_PS   (OFF_D)               // proj [128][68]                       8704
#define OFF_XQT  (OFF_D+8704)          // qT*norm [64][72]                     4608
#define OFF_XKT  (OFF_D+13312)         // kT*norm [64][72]                     4608
// phase3+ view:
#define OFF_SS   (OFF_D)               // S_prev [128][72]                     9216
#define OFF_AS   (OFF_D+9216)          // A [64][68]                           4352
#define OFF_OB   (OFF_D+13568)         // out2 [64][72]                        4608
#define SMEMF    (OFF_D+18176)         // 42752 floats = 171008 B

#define F2U __float_as_uint
#define U2F __uint_as_float

__device__ __forceinline__ float tf32r(float f) {
    uint32 u; asm("cvt.rna.tf32.f32 %0,%1;" : "=r"(u) : "f"(f));
    return U2F(u);
}
__device__ __forceinline__ u64 pk2(float x, float y) {
    u64 r; asm("mov.b64 %0,{%1,%2};" : "=l"(r) : "f"(x), "f"(y)); return r;
}
// D += A*B  (m16n8k8, row.col, tf32 in / f32 acc)
__device__ __forceinline__ void mma8(float* c, uint32 a0, uint32 a1, uint32 a2, uint32 a3,
                                     uint32 b0, uint32 b1) {
    asm volatile("mma.sync.aligned.m16n8k8.row.col.f32.tf32.tf32.f32 "
        "{%0,%1,%2,%3},{%4,%5,%6,%7},{%8,%9},{%0,%1,%2,%3};"
        : "+f"(c[0]), "+f"(c[1]), "+f"(c[2]), "+f"(c[3])
        : "r"(a0), "r"(a1), "r"(a2), "r"(a3), "r"(b0), "r"(b1));
}

__global__ void __launch_bounds__(1024, 1)
k_fused(const float* __restrict__ q, const float* __restrict__ k,
        const float* __restrict__ v, const float* __restrict__ proj,
        float* __restrict__ out) {
    extern __shared__ float sm[];
    const int c = blockIdx.x, h = blockIdx.y, tid = threadIdx.x;

    float* qsT = sm + OFF_QST;
    float* kpT = sm + OFF_KPT;
    float* vs  = sm + OFF_VS;
    float* seg = sm + OFF_SEG;
    float* zq  = sm + OFF_ZQ;
    float* ps  = sm + OFF_PS;
    float* xqT = sm + OFF_XQT;
    float* xkT = sm + OFF_XKT;
    float* Ss  = sm + OFF_SS;
    float* As  = sm + OFF_AS;
    float* ob  = sm + OFF_OB;

    const int base = (h*NNS + c*CC)*DD;
    const int w = tid >> 5, lane = tid & 31;
    const int gid = lane >> 2, tig = lane & 3;

    // ================= phase 0: loads (tf32-rounded into smem) =================
    for (int i = tid; i < MM*DD; i += 1024) {
        int m = i >> 6, d = i & 63;
        ps[m*68 + d] = tf32r(proj[i]);                 // proj row-major [m][d]
    }
    for (int i = tid; i < CC*DD; i += 1024) {
        int n = i >> 6, d = i & 63;
        xqT[d*72 + n] = tf32r(q[base + i] * NORMF);
        xkT[d*72 + n] = tf32r(k[base + i] * NORMF);
        vs[n*72 + d]  = tf32r(v[base + i]);
    }
    __syncthreads();

    // ===== phase 1: featT[m][n] = relu( proj[m,:] . x[n,:] ) + eps  (mma) =====
    // 32 warps: map = w>>4 (q/k); 16 warps cover [128m][64n]: warp tile 16m x 32n.
    {
        const int mp = w >> 4, wl = w & 15;
        const int m0 = 16*(wl >> 1), nb = 32*(wl & 1);
        const float* xT = mp ? xkT : xqT;
        float* oT       = mp ? kpT : qsT;
        float acc[4][4];
        #pragma unroll
        for (int t = 0; t < 4; t++)
            #pragma unroll
            for (int i = 0; i < 4; i++) acc[t][i] = 0.f;
        const float* Ar0 = ps + (m0+gid)*68 + tig;
        const float* Ar1 = Ar0 + 8*68;
        #pragma unroll
        for (int kk = 0; kk < 8; kk++) {
            const int d0 = 8*kk;
            uint32 a0 = F2U(Ar0[d0]),   a1 = F2U(Ar1[d0]);
            uint32 a2 = F2U(Ar0[d0+4]), a3 = F2U(Ar1[d0+4]);
            const float* B0 = xT + (d0+tig)*72 + nb + gid;
            const float* B1 = xT + (d0+tig+4)*72 + nb + gid;
            #pragma unroll
            for (int t = 0; t < 4; t++)
                mma8(acc[t], a0, a1, a2, a3, F2U(B0[8*t]), F2U(B1[8*t]));
        }
        #pragma unroll
        for (int t = 0; t < 4; t++) {
            const int n0 = nb + 8*t;
            float v0 = tf32r(fmaxf(acc[t][0], 0.f) + EPSF);
            float v1 = tf32r(fmaxf(acc[t][1], 0.f) + EPSF);
            float v2 = tf32r(fmaxf(acc[t][2], 0.f) + EPSF);
            float v3 = tf32r(fmaxf(acc[t][3], 0.f) + EPSF);
            *(u64*)&oT[(m0+gid)*72   + n0 + 2*tig] = pk2(v0, v1);
            *(u64*)&oT[(m0+gid+8)*72 + n0 + 2*tig] = pk2(v2, v3);
        }
    }
    __syncthreads();

    // ======== phase 2: S_c = Kp^T V [128m][64d] (mma) -> g_Sc;  z_c ========
    {
        const int m0 = 16*(w >> 2), dp = w & 3;
        float acc[2][4];
        #pragma unroll
        for (int t = 0; t < 2; t++)
            #pragma unroll
            for (int i = 0; i < 4; i++) acc[t][i] = 0.f;
        #pragma unroll
        for (int kk = 0; kk < 8; kk++) {
            const int n0 = 8*kk;
            uint32 a0 = F2U(kpT[(m0+gid)*72   + n0+tig]);
            uint32 a1 = F2U(kpT[(m0+gid+8)*72 + n0+tig]);
            uint32 a2 = F2U(kpT[(m0+gid)*72   + n0+tig+4]);
            uint32 a3 = F2U(kpT[(m0+gid+8)*72 + n0+tig+4]);
            #pragma unroll
            for (int t = 0; t < 2; t++) {
                const int d0 = 16*dp + 8*t;
                uint32 b0 = F2U(vs[(n0+tig)*72   + d0+gid]);
                uint32 b1 = F2U(vs[(n0+tig+4)*72 + d0+gid]);
                mma8(acc[t], a0, a1, a2, a3, b0, b1);
            }
        }
        float* Sg = g_Sc + ((h*NCH + c) << 13);
        #pragma unroll
        for (int t = 0; t < 2; t++) {
            const int d0 = 16*dp + 8*t;
            *(u64*)&Sg[(m0+gid)*64   + d0 + 2*tig] = pk2(acc[t][0], acc[t][1]);
            *(u64*)&Sg[(m0+gid+8)*64 + d0 + 2*tig] = pk2(acc[t][2], acc[t][3]);
        }
    }
    {   // segmented row sums of kpT: 8 segments x 8 n
        const int m = tid & 127, sg = tid >> 7;
        float4 k0 = *(const float4*)&kpT[m*72 + sg*8];
        float4 k1 = *(const float4*)&kpT[m*72 + sg*8 + 4];
        seg[sg*128 + m] = (k0.x+k0.y+k0.z+k0.w) + (k1.x+k1.y+k1.z+k1.w);
    }
    __syncthreads();
    if (tid < MM) {
        float z = 0.f;
        #pragma unroll
        for (int s = 0; s < 8; s++) z += seg[s*128 + tid];
        g_zc[(h*NCH + c)*MM + tid] = z;
    }
    __threadfence();
    __syncthreads();
    if (tid == 0) atomicExch(&g_flag[h*NCH + c], 1);

    // ========== phase 3/4 overlapped ==========
    if (tid < c) {
        while (atomicAdd(&g_flag[h*NCH + tid], 0) == 0) {}
    }
    __syncthreads();
    __threadfence();
    if (tid < 512) {
        // z prefix (4-way) + cumsum + divide (+tf32 re-round of q')
        const int m = tid & 127, qtr = tid >> 7;
        float z = 0.f;
        for (int c2 = qtr; c2 < c; c2 += 4)
            z += g_zc[(h*NCH + c2)*MM + m];
        zq[qtr*128 + m] = z;
        asm volatile("bar.sync 1, 512;" ::: "memory");
        float run = zq[m] + zq[128 + m] + zq[256 + m] + zq[384 + m];
        #pragma unroll
        for (int s = 0; s < 3; s++)
            if (s < qtr) run += seg[(2*s)*128 + m] + seg[(2*s+1)*128 + m];
        float* kr = &kpT[m*72 + qtr*16];
        float* qr = &qsT[m*72 + qtr*16];
        #pragma unroll
        for (int n = 0; n < 16; n++) {
            run += kr[n];
            qr[n] = tf32r(__fdividef(qr[n], run));
        }
    } else {
        // S_prev accumulation from L2 -> Ss (tf32-rounded, stride 72)
        const int i0 = (tid - 512) * 16;
        const int mrow = i0 >> 6, dcol = i0 & 63;
        float4 a0 = {0,0,0,0}, a1 = {0,0,0,0}, a2 = {0,0,0,0}, a3 = {0,0,0,0};
        for (int c2 = 0; c2 < c; c2++) {
            const float4* p = (const float4*)(g_Sc + ((h*NCH + c2) << 13) + i0);
            float4 t0 = p[0], t1 = p[1], t2 = p[2], t3 = p[3];
            a0.x += t0.x; a0.y += t0.y; a0.z += t0.z; a0.w += t0.w;
            a1.x += t1.x; a1.y += t1.y; a1.z += t1.z; a1.w += t1.w;
            a2.x += t2.x; a2.y += t2.y; a2.z += t2.z; a2.w += t2.w;
            a3.x += t3.x; a3.y += t3.y; a3.z += t3.z; a3.w += t3.w;
        }
        float* dst = &Ss[mrow*72 + dcol];
        dst[0]=tf32r(a0.x);  dst[1]=tf32r(a0.y);  dst[2]=tf32r(a0.z);  dst[3]=tf32r(a0.w);
        dst[4]=tf32r(a1.x);  dst[5]=tf32r(a1.y);  dst[6]=tf32r(a1.z);  dst[7]=tf32r(a1.w);
        dst[8]=tf32r(a2.x);  dst[9]=tf32r(a2.y);  dst[10]=tf32r(a2.z); dst[11]=tf32r(a2.w);
        dst[12]=tf32r(a3.x); dst[13]=tf32r(a3.y); dst[14]=tf32r(a3.z); dst[15]=tf32r(a3.w);
    }
    __syncthreads();

    // ============ phase 5: A = tril(Q'Kp^T) | out2 = Q'S_prev (mma, K=128) ============
    if (w < 16) {
        const int n0 = 16*(w & 3), jp = w >> 2;
        float acc[2][4];
        #pragma unroll
        for (int t = 0; t < 2; t++)
            #pragma unroll
            for (int i = 0; i < 4; i++) acc[t][i] = 0.f;
        #pragma unroll 4
        for (int kk = 0; kk < 16; kk++) {
            const int m0 = 8*kk;
            uint32 a0 = F2U(qsT[(m0+tig)*72   + n0+gid]);
            uint32 a1 = F2U(qsT[(m0+tig)*72   + n0+gid+8]);
            uint32 a2 = F2U(qsT[(m0+tig+4)*72 + n0+gid]);
            uint32 a3 = F2U(qsT[(m0+tig+4)*72 + n0+gid+8]);
            #pragma unroll
            for (int t = 0; t < 2; t++) {
                const int j0 = 16*jp + 8*t;
                uint32 b0 = F2U(kpT[(m0+tig)*72   + j0+gid]);
                uint32 b1 = F2U(kpT[(m0+tig+4)*72 + j0+gid]);
                mma8(acc[t], a0, a1, a2, a3, b0, b1);
            }
        }
        #pragma unroll
        for (int t = 0; t < 2; t++) {
            const int j0 = 16*jp + 8*t;
            const int n1 = n0 + gid, n2 = n1 + 8, j = j0 + 2*tig;
            float v0 = (j   <= n1) ? tf32r(acc[t][0]) : 0.f;
            float v1 = (j+1 <= n1) ? tf32r(acc[t][1]) : 0.f;
            float v2 = (j   <= n2) ? tf32r(acc[t][2]) : 0.f;
            float v3 = (j+1 <= n2) ? tf32r(acc[t][3]) : 0.f;
            *(u64*)&As[n1*68 + j] = pk2(v0, v1);
            *(u64*)&As[n2*68 + j] = pk2(v2, v3);
        }
    } else {
        const int wl = w - 16;
        const int n0 = 16*(wl & 3), dp = wl >> 2;
        float acc[2][4];
        #pragma unroll
        for (int t = 0; t < 2; t++)
            #pragma unroll
            for (int i = 0; i < 4; i++) acc[t][i] = 0.f;
        #pragma unroll 4
        for (int kk = 0; kk < 16; kk++) {
            const int m0 = 8*kk;
            uint32 a0 = F2U(qsT[(m0+tig)*72   + n0+gid]);
            uint32 a1 = F2U(qsT[(m0+tig)*72   + n0+gid+8]);
            uint32 a2 = F2U(qsT[(m0+tig+4)*72 + n0+gid]);
            uint32 a3 = F2U(qsT[(m0+tig+4)*72 + n0+gid+8]);
            #pragma unroll
            for (int t = 0; t < 2; t++) {
                const int d0 = 16*dp + 8*t;
                uint32 b0 = F2U(Ss[(m0+tig)*72   + d0+gid]);
                uint32 b1 = F2U(Ss[(m0+tig+4)*72 + d0+gid]);
                mma8(acc[t], a0, a1, a2, a3, b0, b1);
            }
        }
        #pragma unroll
        for (int t = 0; t < 2; t++) {
            const int d0 = 16*dp + 8*t;
            *(u64*)&ob[(n0+gid)*72   + d0 + 2*tig] = pk2(acc[t][0], acc[t][1]);
            *(u64*)&ob[(n0+gid+8)*72 + d0 + 2*tig] = pk2(acc[t][2], acc[t][3]);
        }
    }
    __syncthreads();

    // ============ phase 6: out = A @ V + out2 (mma, C-init from ob) ============
    {
        const int n0 = 16*(w & 3), d0 = 8*(w >> 2);
        float acc[4];
        float2 lo = *(const float2*)&ob[(n0+gid)*72   + d0 + 2*tig];
        float2 hi = *(const float2*)&ob[(n0+gid+8)*72 + d0 + 2*tig];
        acc[0] = lo.x; acc[1] = lo.y; acc[2] = hi.x; acc[3] = hi.y;
        #pragma unroll
        for (int kk = 0; kk < 8; kk++) {
            const int j0 = 8*kk;
            uint32 a0 = F2U(As[(n0+gid)*68   + j0+tig]);
            uint32 a1 = F2U(As[(n0+gid+8)*68 + j0+tig]);
            uint32 a2 = F2U(As[(n0+gid)*68   + j0+tig+4]);
            uint32 a3 = F2U(As[(n0+gid+8)*68 + j0+tig+4]);
            uint32 b0 = F2U(vs[(j0+tig)*72   + d0+gid]);
            uint32 b1 = F2U(vs[(j0+tig+4)*72 + d0+gid]);
            mma8(acc, a0, a1, a2, a3, b0, b1);
        }
        float2 o0; o0.x = acc[0]; o0.y = acc[1];
        float2 o1; o1.x = acc[2]; o1.y = acc[3];
        *(float2*)&out[base + (n0+gid)*64   + d0 + 2*tig] = o0;
        *(float2*)&out[base + (n0+gid+8)*64 + d0 + 2*tig] = o1;
    }
}

// ============================================================
extern "C" void kernel_launch(void* const* d_in, const int* in_sizes, int n_in,
                              void* d_out, int out_size) {
    const float* q    = (const float*)d_in[0];
    const float* k    = (const float*)d_in[1];
    const float* v    = (const float*)d_in[2];
    const float* proj = (const float*)d_in[3];
    float* out = (float*)d_out;

    const size_t smem = SMEMF * sizeof(float);   // 171008 B
    cudaFuncSetAttribute(k_fused, cudaFuncAttributeMaxDynamicSharedMemorySize, (int)smem);
    k_fused<<<dim3(NCH, HH), 1024, smem>>>(q, k, v, proj, out);
}